// round 2
// baseline (speedup 1.0000x reference)
#include <cuda_runtime.h>

// ---------------------------------------------------------------------------
// GIN encoder, deterministic version (no float atomics anywhere).
// Per layer: CSR gather aggregation + MLP(300->600 relu ->300) + BN(+relu).
// ---------------------------------------------------------------------------
#define N_NODES 50000
#define M_PAD   50048           // 391 * 128, GEMM M-tile friendly
#define EMB     300
#define EMB2    600
#define N_EDGES 800000
#define NLAYER  5
#define NCHUNK  391             // BN row chunks of 128

// Scratch state (allocation-free: device globals)
__device__ float g_h   [M_PAD * EMB];          // 60 MB
__device__ float g_agg [M_PAD * EMB];          // 60 MB (also GEMM2 out)
__device__ float g_hid [M_PAD * EMB2];         // 120 MB
__device__ float g_stats[2 * EMB];             // BN scale / shift
__device__ float g_part [NCHUNK * 2 * EMB];    // BN partial sums
__device__ int   g_deg [N_NODES];
__device__ int   g_cur [N_NODES];
__device__ int   g_off [N_NODES + 1];
__device__ int   g_eid [N_EDGES];
__device__ unsigned char g_combo[N_EDGES];

// ---------------------------------------------------------------------------
// h[i] = x_emb[x[i,0]] + x_emb[x[i,1]]
// ---------------------------------------------------------------------------
__global__ void node_emb_kernel(const int* __restrict__ x,
                                const float* __restrict__ xemb) {
    int idx = blockIdx.x * blockDim.x + threadIdx.x;       // over N_NODES * 75 float4
    if (idx >= N_NODES * 75) return;
    int row = idx / 75;
    int c4  = idx - row * 75;
    int a = x[2 * row];
    int b = x[2 * row + 1];
    float4 va = ((const float4*)(xemb + a * EMB))[c4];
    float4 vb = ((const float4*)(xemb + b * EMB))[c4];
    va.x += vb.x; va.y += vb.y; va.z += vb.z; va.w += vb.w;
    ((float4*)g_h)[idx] = va;
}

// ---------------------------------------------------------------------------
// CSR build (once per call). Integer atomics only -> deterministic counts;
// bucket order is made deterministic by a per-node sort afterwards.
// ---------------------------------------------------------------------------
__global__ void reset_kernel() {
    int i = blockIdx.x * blockDim.x + threadIdx.x;
    if (i < N_NODES) { g_deg[i] = 0; g_cur[i] = 0; }
}

__global__ void combo_hist_kernel(const int* __restrict__ ei,
                                  const int* __restrict__ ea) {
    int e = blockIdx.x * blockDim.x + threadIdx.x;
    if (e >= N_EDGES) return;
    g_combo[e] = (unsigned char)(ea[2 * e] * 3 + ea[2 * e + 1]);
    atomicAdd(&g_deg[ei[N_EDGES + e]], 1);
}

__global__ void scan_kernel() {                 // single block, 1024 threads
    __shared__ int s[1024];
    __shared__ int carry;
    int tid = threadIdx.x;
    if (tid == 0) carry = 0;
    __syncthreads();
    for (int base = 0; base < N_NODES; base += 1024) {
        int v = (base + tid < N_NODES) ? g_deg[base + tid] : 0;
        s[tid] = v;
        __syncthreads();
        #pragma unroll
        for (int d = 1; d < 1024; d <<= 1) {
            int t = (tid >= d) ? s[tid - d] : 0;
            __syncthreads();
            s[tid] += t;
            __syncthreads();
        }
        if (base + tid < N_NODES) g_off[base + tid + 1] = carry + s[tid];
        __syncthreads();
        if (tid == 1023) carry += s[1023];
        __syncthreads();
    }
    if (tid == 0) g_off[0] = 0;
}

__global__ void fill_kernel(const int* __restrict__ ei) {
    int e = blockIdx.x * blockDim.x + threadIdx.x;
    if (e >= N_EDGES) return;
    int dst = ei[N_EDGES + e];
    int slot = atomicAdd(&g_cur[dst], 1);
    g_eid[g_off[dst] + slot] = e;
}

__global__ void sort_kernel() {                 // thread per node: insertion sort
    int n = blockIdx.x * blockDim.x + threadIdx.x;
    if (n >= N_NODES) return;
    int a = g_off[n], b = g_off[n + 1];
    for (int i = a + 1; i < b; i++) {
        int key = g_eid[i];
        int j = i - 1;
        while (j >= a && g_eid[j] > key) { g_eid[j + 1] = g_eid[j]; j--; }
        g_eid[j + 1] = key;
    }
}

// ---------------------------------------------------------------------------
// Gather aggregation: one warp per node, fixed edge order -> deterministic.
// agg[n] = h[n] + ee(4)+ee(0)  +  sum_{e in CSR(n)} ( h[src(e)] + comb[c(e)] )
// ---------------------------------------------------------------------------
__global__ void gather_kernel(const int* __restrict__ ei,
                              const float* __restrict__ eemb, int layer) {
    __shared__ __align__(16) float comb[9 * EMB];
    __shared__ __align__(16) float selfc[EMB];
    const float* emb = eemb + layer * 6 * EMB;
    for (int i = threadIdx.x; i < 9 * EMB; i += blockDim.x) {
        int c = i / EMB;
        int d = i - c * EMB;
        comb[i] = emb[(c / 3) * EMB + d] + emb[(c % 3) * EMB + d];
    }
    for (int i = threadIdx.x; i < EMB; i += blockDim.x)
        selfc[i] = emb[4 * EMB + i] + emb[0 * EMB + i];
    __syncthreads();

    int lane = threadIdx.x & 31;
    int node = (blockIdx.x * blockDim.x + threadIdx.x) >> 5;
    if (node >= M_PAD) return;

    float4 acc[3];
    #pragma unroll
    for (int k = 0; k < 3; k++) acc[k] = make_float4(0.f, 0.f, 0.f, 0.f);

    if (node < N_NODES) {
        const float4* hn = (const float4*)(g_h + node * EMB);
        const float4* sc = (const float4*)selfc;
        #pragma unroll
        for (int k = 0; k < 3; k++) {
            int j = lane + k * 32;
            if (j < 75) {
                float4 a = hn[j], b = sc[j];
                acc[k].x = a.x + b.x; acc[k].y = a.y + b.y;
                acc[k].z = a.z + b.z; acc[k].w = a.w + b.w;
            }
        }
        int beg = g_off[node], end = g_off[node + 1];
        for (int idx = beg; idx < end; idx++) {
            int e   = g_eid[idx];
            int src = ei[e];
            int c   = g_combo[e];
            const float4* hs = (const float4*)(g_h + src * EMB);
            const float4* cb = (const float4*)(comb + c * EMB);
            #pragma unroll
            for (int k = 0; k < 3; k++) {
                int j = lane + k * 32;
                if (j < 75) {
                    float4 a = hs[j], b = cb[j];
                    acc[k].x += a.x + b.x; acc[k].y += a.y + b.y;
                    acc[k].z += a.z + b.z; acc[k].w += a.w + b.w;
                }
            }
        }
    }
    float4* out = (float4*)(g_agg + node * EMB);
    #pragma unroll
    for (int k = 0; k < 3; k++) {
        int j = lane + k * 32;
        if (j < 75) out[j] = acc[k];
    }
}

// ---------------------------------------------------------------------------
// SGEMM:  C[M_PAD, NDIM] = A[M_PAD, KDIM] @ W[KDIM, NDIM] + bias (+relu)
// ---------------------------------------------------------------------------
template <bool FIRST>
__global__ void __launch_bounds__(256) gemm_kernel(const float* __restrict__ Wall,
                                                   const float* __restrict__ ball,
                                                   int layer) {
    constexpr int KDIM = FIRST ? EMB : EMB2;
    constexpr int NDIM = FIRST ? EMB2 : EMB;
    constexpr int BM = 128, BN = 128, BK = 10, TM = 8, TN = 8;

    const float* __restrict__ A = FIRST ? g_agg : g_hid;
    float*       C              = FIRST ? g_hid : g_agg;
    const float* W    = Wall + layer * KDIM * NDIM;
    const float* bias = ball + layer * NDIM;

    __shared__ float As[BM][BK];
    __shared__ float Bs[BK][BN];

    int tid = threadIdx.x;
    int tx = tid & 15;
    int ty = tid >> 4;
    int m0 = blockIdx.x * BM;
    int n0 = blockIdx.y * BN;
    int row0 = ty * TM;
    int col0 = tx * TN;

    float acc[TM][TN];
    #pragma unroll
    for (int i = 0; i < TM; i++)
        #pragma unroll
        for (int j = 0; j < TN; j++) acc[i][j] = 0.f;

    for (int kt = 0; kt < KDIM; kt += BK) {
        #pragma unroll
        for (int i = 0; i < (BM * BK) / 256; i++) {
            int idx = tid + i * 256;
            int r = idx / BK;
            int c = idx - r * BK;
            As[r][c] = A[(m0 + r) * KDIM + kt + c];
        }
        #pragma unroll
        for (int i = 0; i < (BK * BN) / 256; i++) {
            int idx = tid + i * 256;
            int k = idx >> 7;
            int n = idx & 127;
            float v = 0.f;
            if (n0 + n < NDIM) v = W[(kt + k) * NDIM + n0 + n];
            Bs[k][n] = v;
        }
        __syncthreads();

        #pragma unroll
        for (int k = 0; k < BK; k++) {
            float a[TM], b[TN];
            #pragma unroll
            for (int i = 0; i < TM; i++) a[i] = As[row0 + i][k];
            #pragma unroll
            for (int j = 0; j < TN; j++) b[j] = Bs[k][col0 + j];
            #pragma unroll
            for (int i = 0; i < TM; i++)
                #pragma unroll
                for (int j = 0; j < TN; j++)
                    acc[i][j] += a[i] * b[j];
        }
        __syncthreads();
    }

    #pragma unroll
    for (int i = 0; i < TM; i++) {
        int m = m0 + row0 + i;
        #pragma unroll
        for (int j = 0; j < TN; j++) {
            int n = n0 + col0 + j;
            if (n < NDIM) {
                float v = acc[i][j] + bias[n];
                if (FIRST) v = fmaxf(v, 0.f);
                C[m * NDIM + n] = v;
            }
        }
    }
}

// ---------------------------------------------------------------------------
// BatchNorm, fully deterministic: fixed-partition partials + fixed-order final
// ---------------------------------------------------------------------------
__global__ void bn_part_kernel() {              // grid NCHUNK, block 320
    int c = threadIdx.x;
    if (c >= EMB) return;
    int r0   = blockIdx.x * 128;
    int rend = min(r0 + 128, N_NODES);
    float s = 0.f, q = 0.f;
    for (int r = r0; r < rend; r++) {
        float v = g_agg[r * EMB + c];
        s += v;
        q += v * v;
    }
    g_part[blockIdx.x * 2 * EMB + c]       = s;
    g_part[blockIdx.x * 2 * EMB + EMB + c] = q;
}

__global__ void bn_final_kernel(const float* __restrict__ gamma,
                                const float* __restrict__ beta, int layer) {
    int c = threadIdx.x;
    if (c >= EMB) return;
    float s = 0.f, q = 0.f;
    for (int b = 0; b < NCHUNK; b++) {          // fixed order
        s += g_part[b * 2 * EMB + c];
        q += g_part[b * 2 * EMB + EMB + c];
    }
    const float inv_n = 1.0f / (float)N_NODES;
    float mean = s * inv_n;
    float var  = q * inv_n - mean * mean;
    float sc = gamma[layer * EMB + c] * rsqrtf(var + 1e-5f);
    float sh = beta[layer * EMB + c] - mean * sc;
    g_stats[c]       = sc;
    g_stats[EMB + c] = sh;
}

__global__ void bn_apply_kernel(float* __restrict__ dst, int do_relu) {
    int idx = blockIdx.x * blockDim.x + threadIdx.x;       // over N_NODES * 75
    if (idx >= N_NODES * 75) return;
    int c = (idx % 75) * 4;
    float4 v = ((const float4*)g_agg)[idx];
    float r0 = v.x * g_stats[c + 0] + g_stats[EMB + c + 0];
    float r1 = v.y * g_stats[c + 1] + g_stats[EMB + c + 1];
    float r2 = v.z * g_stats[c + 2] + g_stats[EMB + c + 2];
    float r3 = v.w * g_stats[c + 3] + g_stats[EMB + c + 3];
    if (do_relu) {
        r0 = fmaxf(r0, 0.f); r1 = fmaxf(r1, 0.f);
        r2 = fmaxf(r2, 0.f); r3 = fmaxf(r3, 0.f);
    }
    float* o = dst ? dst : g_h;
    ((float4*)o)[idx] = make_float4(r0, r1, r2, r3);
}

// ---------------------------------------------------------------------------
extern "C" void kernel_launch(void* const* d_in, const int* in_sizes, int n_in,
                              void* d_out, int out_size) {
    const int*   x     = (const int*)d_in[0];
    const int*   ei    = (const int*)d_in[1];
    const int*   ea    = (const int*)d_in[2];
    const float* xemb  = (const float*)d_in[3];
    const float* eemb  = (const float*)d_in[4];
    const float* W1    = (const float*)d_in[5];
    const float* b1    = (const float*)d_in[6];
    const float* W2    = (const float*)d_in[7];
    const float* b2    = (const float*)d_in[8];
    const float* gamma = (const float*)d_in[9];
    const float* beta  = (const float*)d_in[10];
    float* out = (float*)d_out;

    node_emb_kernel<<<(N_NODES * 75 + 255) / 256, 256>>>(x, xemb);

    // CSR build (deterministic after sort)
    reset_kernel<<<(N_NODES + 255) / 256, 256>>>();
    combo_hist_kernel<<<(N_EDGES + 255) / 256, 256>>>(ei, ea);
    scan_kernel<<<1, 1024>>>();
    fill_kernel<<<(N_EDGES + 255) / 256, 256>>>(ei);
    sort_kernel<<<(N_NODES + 255) / 256, 256>>>();

    for (int layer = 0; layer < NLAYER; layer++) {
        gather_kernel<<<(M_PAD * 32 + 255) / 256, 256>>>(ei, eemb, layer);
        gemm_kernel<true ><<<dim3(M_PAD / 128, (EMB2 + 127) / 128), 256>>>(W1, b1, layer);
        gemm_kernel<false><<<dim3(M_PAD / 128, (EMB  + 127) / 128), 256>>>(W2, b2, layer);
        bn_part_kernel<<<NCHUNK, 320>>>();
        bn_final_kernel<<<1, 320>>>(gamma, beta, layer);
        bn_apply_kernel<<<(N_NODES * 75 + 255) / 256, 256>>>(
            layer == NLAYER - 1 ? out : nullptr, layer != NLAYER - 1 ? 1 : 0);
    }
}

// round 5
// speedup vs baseline: 2.9162x; 2.9162x over previous
#include <cuda_runtime.h>
#include <cuda_bf16.h>
#include <cstdint>

// ---------------------------------------------------------------------------
// GIN encoder, deterministic, GEMMs via mma.sync bf16 (hi/lo split, 3-MMA).
// ---------------------------------------------------------------------------
#define N_NODES 50000
#define M_PAD   50048           // 391 * 128
#define EMB     300
#define EMB2    600
#define N_EDGES 800000
#define NLAYER  5
#define NCHUNK  391
#define NBLK256 196             // ceil(50000/256)

// GEMM1: K=300 (pad 320), N=600 (pad 640). GEMM2: K=600 (pad 608), N=300 (pad 384).
#define KP1 320
#define NP1 640
#define KP2 608
#define NP2 384

// Scratch state (allocation-free: device globals)
__device__ float g_h   [M_PAD * EMB];
__device__ float g_agg [M_PAD * EMB];
__device__ float g_hid [M_PAD * EMB2];
__device__ float g_stats[2 * EMB];
__device__ float g_part [NCHUNK * 2 * EMB];
__device__ int   g_deg [N_NODES];
__device__ int   g_cur [N_NODES];
__device__ int   g_off [N_NODES + 1];
__device__ int   g_eid [N_EDGES];
__device__ int   g_bsum[256];
__device__ unsigned char g_combo[N_EDGES];
// pre-transposed, padded, bf16-split weights: [layer][NPAD][KPAD]
__device__ __align__(16) __nv_bfloat16 g_w1h[NLAYER * NP1 * KP1];
__device__ __align__(16) __nv_bfloat16 g_w1l[NLAYER * NP1 * KP1];
__device__ __align__(16) __nv_bfloat16 g_w2h[NLAYER * NP2 * KP2];
__device__ __align__(16) __nv_bfloat16 g_w2l[NLAYER * NP2 * KP2];

#define MMA16816(d, a, b0, b1)                                                \
    asm volatile("mma.sync.aligned.m16n8k16.row.col.f32.bf16.bf16.f32 "       \
        "{%0,%1,%2,%3}, {%4,%5,%6,%7}, {%8,%9}, {%0,%1,%2,%3};"               \
        : "+f"((d)[0]), "+f"((d)[1]), "+f"((d)[2]), "+f"((d)[3])              \
        : "r"((a)[0]), "r"((a)[1]), "r"((a)[2]), "r"((a)[3]),                 \
          "r"(b0), "r"(b1))

// ---------------------------------------------------------------------------
// h[i] = x_emb[x[i,0]] + x_emb[x[i,1]]
// ---------------------------------------------------------------------------
__global__ void node_emb_kernel(const int* __restrict__ x,
                                const float* __restrict__ xemb) {
    int idx = blockIdx.x * blockDim.x + threadIdx.x;
    if (idx >= N_NODES * 75) return;
    int row = idx / 75;
    int c4  = idx - row * 75;
    int a = x[2 * row];
    int b = x[2 * row + 1];
    float4 va = ((const float4*)(xemb + a * EMB))[c4];
    float4 vb = ((const float4*)(xemb + b * EMB))[c4];
    va.x += vb.x; va.y += vb.y; va.z += vb.z; va.w += vb.w;
    ((float4*)g_h)[idx] = va;
}

// ---------------------------------------------------------------------------
// Weight prep: transpose to [N][K], zero-pad, bf16 hi/lo split. Once per call.
// ---------------------------------------------------------------------------
__global__ void prep_w1_kernel(const float* __restrict__ W1) {
    int idx = blockIdx.x * blockDim.x + threadIdx.x;
    if (idx >= NLAYER * NP1 * KP1) return;
    int layer = idx / (NP1 * KP1);
    int rem = idx - layer * NP1 * KP1;
    int n = rem / KP1, k = rem - n * KP1;
    float v = (n < EMB2 && k < EMB) ? W1[layer * EMB * EMB2 + k * EMB2 + n] : 0.f;
    __nv_bfloat16 h = __float2bfloat16(v);
    g_w1h[idx] = h;
    g_w1l[idx] = __float2bfloat16(v - __bfloat162float(h));
}
__global__ void prep_w2_kernel(const float* __restrict__ W2) {
    int idx = blockIdx.x * blockDim.x + threadIdx.x;
    if (idx >= NLAYER * NP2 * KP2) return;
    int layer = idx / (NP2 * KP2);
    int rem = idx - layer * NP2 * KP2;
    int n = rem / KP2, k = rem - n * KP2;
    float v = (n < EMB && k < EMB2) ? W2[layer * EMB2 * EMB + k * EMB + n] : 0.f;
    __nv_bfloat16 h = __float2bfloat16(v);
    g_w2h[idx] = h;
    g_w2l[idx] = __float2bfloat16(v - __bfloat162float(h));
}

// ---------------------------------------------------------------------------
// CSR build (deterministic after per-node sort)
// ---------------------------------------------------------------------------
__global__ void reset_kernel() {
    int i = blockIdx.x * blockDim.x + threadIdx.x;
    if (i < N_NODES) { g_deg[i] = 0; g_cur[i] = 0; }
}
__global__ void combo_hist_kernel(const int* __restrict__ ei,
                                  const int* __restrict__ ea) {
    int e = blockIdx.x * blockDim.x + threadIdx.x;
    if (e >= N_EDGES) return;
    g_combo[e] = (unsigned char)(ea[2 * e] * 3 + ea[2 * e + 1]);
    atomicAdd(&g_deg[ei[N_EDGES + e]], 1);
}
__global__ void scan1_kernel() {
    __shared__ int s[256];
    int tid = threadIdx.x;
    int i = blockIdx.x * 256 + tid;
    s[tid] = (i < N_NODES) ? g_deg[i] : 0;
    __syncthreads();
    #pragma unroll
    for (int d = 1; d < 256; d <<= 1) {
        int t = (tid >= d) ? s[tid - d] : 0;
        __syncthreads();
        s[tid] += t;
        __syncthreads();
    }
    if (i < N_NODES) g_off[i + 1] = s[tid];
    if (tid == 255) g_bsum[blockIdx.x] = s[255];
}
__global__ void scan2_kernel() {
    __shared__ int s[256];
    int tid = threadIdx.x;
    s[tid] = (tid < NBLK256) ? g_bsum[tid] : 0;
    __syncthreads();
    #pragma unroll
    for (int d = 1; d < 256; d <<= 1) {
        int t = (tid >= d) ? s[tid - d] : 0;
        __syncthreads();
        s[tid] += t;
        __syncthreads();
    }
    g_bsum[tid] = s[tid];
}
__global__ void scan3_kernel() {
    int i = blockIdx.x * 256 + threadIdx.x;
    if (i < N_NODES && blockIdx.x > 0) g_off[i + 1] += g_bsum[blockIdx.x - 1];
    if (i == 0) g_off[0] = 0;
}
__global__ void fill_kernel(const int* __restrict__ ei) {
    int e = blockIdx.x * blockDim.x + threadIdx.x;
    if (e >= N_EDGES) return;
    int dst = ei[N_EDGES + e];
    int slot = atomicAdd(&g_cur[dst], 1);
    g_eid[g_off[dst] + slot] = e;
}
__global__ void sort_kernel() {
    int n = blockIdx.x * blockDim.x + threadIdx.x;
    if (n >= N_NODES) return;
    int a = g_off[n], b = g_off[n + 1];
    for (int i = a + 1; i < b; i++) {
        int key = g_eid[i];
        int j = i - 1;
        while (j >= a && g_eid[j] > key) { g_eid[j + 1] = g_eid[j]; j--; }
        g_eid[j + 1] = key;
    }
}

// ---------------------------------------------------------------------------
// Gather aggregation: one warp per node, fixed edge order -> deterministic
// ---------------------------------------------------------------------------
__global__ void gather_kernel(const int* __restrict__ ei,
                              const float* __restrict__ eemb, int layer) {
    __shared__ __align__(16) float comb[9 * EMB];
    __shared__ __align__(16) float selfc[EMB];
    const float* emb = eemb + layer * 6 * EMB;
    for (int i = threadIdx.x; i < 9 * EMB; i += blockDim.x) {
        int c = i / EMB;
        int d = i - c * EMB;
        comb[i] = emb[(c / 3) * EMB + d] + emb[(c % 3) * EMB + d];
    }
    for (int i = threadIdx.x; i < EMB; i += blockDim.x)
        selfc[i] = emb[4 * EMB + i] + emb[0 * EMB + i];
    __syncthreads();

    int lane = threadIdx.x & 31;
    int node = (blockIdx.x * blockDim.x + threadIdx.x) >> 5;
    if (node >= M_PAD) return;

    float4 acc[3];
    #pragma unroll
    for (int k = 0; k < 3; k++) acc[k] = make_float4(0.f, 0.f, 0.f, 0.f);

    if (node < N_NODES) {
        const float4* hn = (const float4*)(g_h + node * EMB);
        const float4* sc = (const float4*)selfc;
        #pragma unroll
        for (int k = 0; k < 3; k++) {
            int j = lane + k * 32;
            if (j < 75) {
                float4 a = hn[j], b = sc[j];
                acc[k].x = a.x + b.x; acc[k].y = a.y + b.y;
                acc[k].z = a.z + b.z; acc[k].w = a.w + b.w;
            }
        }
        int beg = g_off[node], end = g_off[node + 1];
        for (int idx = beg; idx < end; idx++) {
            int e   = g_eid[idx];
            int src = ei[e];
            int c   = g_combo[e];
            const float4* hs = (const float4*)(g_h + src * EMB);
            const float4* cb = (const float4*)(comb + c * EMB);
            #pragma unroll
            for (int k = 0; k < 3; k++) {
                int j = lane + k * 32;
                if (j < 75) {
                    float4 a = hs[j], b = cb[j];
                    acc[k].x += a.x + b.x; acc[k].y += a.y + b.y;
                    acc[k].z += a.z + b.z; acc[k].w += a.w + b.w;
                }
            }
        }
    }
    float4* out = (float4*)(g_agg + node * EMB);
    #pragma unroll
    for (int k = 0; k < 3; k++) {
        int j = lane + k * 32;
        if (j < 75) out[j] = acc[k];
    }
}

// ---------------------------------------------------------------------------
// mma.sync bf16x3 GEMM: C[M_PAD,NDIM] = A @ W + bias (+relu)
// FIRST:  A=g_agg (K=300,KP=320), W=g_w1*, C=g_hid (N=600), relu
// !FIRST: A=g_hid (K=600,KP=608), W=g_w2*, C=g_agg (N=300)
// 128x128 CTA tile, BK=32, 8 warps: warp tile 32(M) x 64(N).
// ---------------------------------------------------------------------------
template <bool FIRST>
__global__ void __launch_bounds__(256, 2) mma_gemm_kernel(const float* __restrict__ ball,
                                                          int layer) {
    constexpr int KDIM = FIRST ? EMB : EMB2;
    constexpr int NDIM = FIRST ? EMB2 : EMB;
    constexpr int KPAD = FIRST ? KP1 : KP2;
    constexpr int NPAD = FIRST ? NP1 : NP2;
    constexpr int NKB  = KPAD / 32;

    const float* __restrict__ A  = FIRST ? g_agg : g_hid;
    float*       C               = FIRST ? g_hid : g_agg;
    const __nv_bfloat16* __restrict__ Bh = FIRST ? g_w1h : g_w2h;
    const __nv_bfloat16* __restrict__ Bl = FIRST ? g_w1l : g_w2l;

    __shared__ __align__(16) __nv_bfloat16 sAh[128][40];
    __shared__ __align__(16) __nv_bfloat16 sAl[128][40];
    __shared__ __align__(16) __nv_bfloat16 sBh[128][40];
    __shared__ __align__(16) __nv_bfloat16 sBl[128][40];

    int tid  = threadIdx.x;
    int lane = tid & 31;
    int wid  = tid >> 5;
    int wm   = (wid & 3) * 32;        // warp M offset within CTA tile
    int wn   = (wid >> 2) * 64;       // warp N offset
    int m0   = blockIdx.x * 128;
    int n0   = blockIdx.y * 128;

    float acc[2][8][4];
    #pragma unroll
    for (int mt = 0; mt < 2; mt++)
        #pragma unroll
        for (int nt = 0; nt < 8; nt++)
            #pragma unroll
            for (int q = 0; q < 4; q++) acc[mt][nt][q] = 0.f;

    const size_t bbase = ((size_t)layer * NPAD + n0) * KPAD;

    for (int kb = 0; kb < NKB; kb++) {
        // --- A tile: 128x32 f32, on-the-fly bf16 hi/lo split ---
        // 128 rows x 32 cols = 1024 float4 over 256 threads (4 iters)
        #pragma unroll
        for (int i = 0; i < 4; i++) {
            int v = tid + i * 256;            // 0..1023
            int r = v >> 3;                   // 0..127
            int c4 = (v & 7) * 4;             // 0..28
            int col = kb * 32 + c4;
            float4 f = make_float4(0.f, 0.f, 0.f, 0.f);
            if (col + 4 <= KDIM)
                f = *(const float4*)(A + (size_t)(m0 + r) * KDIM + col);
            __nv_bfloat16 hx = __float2bfloat16(f.x);
            __nv_bfloat16 hy = __float2bfloat16(f.y);
            __nv_bfloat16 hz = __float2bfloat16(f.z);
            __nv_bfloat16 hw = __float2bfloat16(f.w);
            __nv_bfloat162* ph = (__nv_bfloat162*)&sAh[r][c4];
            ph[0] = __nv_bfloat162(hx, hy);
            ph[1] = __nv_bfloat162(hz, hw);
            __nv_bfloat162* pl = (__nv_bfloat162*)&sAl[r][c4];
            pl[0] = __nv_bfloat162(__float2bfloat16(f.x - __bfloat162float(hx)),
                                   __float2bfloat16(f.y - __bfloat162float(hy)));
            pl[1] = __nv_bfloat162(__float2bfloat16(f.z - __bfloat162float(hz)),
                                   __float2bfloat16(f.w - __bfloat162float(hw)));
        }
        // --- B tiles: 128(N-rows) x 32(K) bf16, pre-split ---
        // 128 rows x 4 uint4/row = 512 uint4 over 256 threads (2 iters)
        #pragma unroll
        for (int i = 0; i < 2; i++) {
            int v = tid + i * 256;            // 0..511
            int r = v >> 2;                   // 0..127  (FIXED: was v>>1, OOB)
            int c8 = (v & 3) * 8;             // 0,8,16,24
            size_t ga = bbase + (size_t)r * KPAD + kb * 32 + c8;
            *(uint4*)&sBh[r][c8] = *(const uint4*)(Bh + ga);
            *(uint4*)&sBl[r][c8] = *(const uint4*)(Bl + ga);
        }
        __syncthreads();

        #pragma unroll
        for (int c = 0; c < 2; c++) {
            int k0 = c * 16 + (lane & 3) * 2;
            int ma = wm + (lane >> 2);
            uint32_t ah[2][4], al[2][4];
            #pragma unroll
            for (int mt = 0; mt < 2; mt++) {
                int m = ma + mt * 16;
                ah[mt][0] = *(const uint32_t*)&sAh[m    ][k0    ];
                ah[mt][1] = *(const uint32_t*)&sAh[m + 8][k0    ];
                ah[mt][2] = *(const uint32_t*)&sAh[m    ][k0 + 8];
                ah[mt][3] = *(const uint32_t*)&sAh[m + 8][k0 + 8];
                al[mt][0] = *(const uint32_t*)&sAl[m    ][k0    ];
                al[mt][1] = *(const uint32_t*)&sAl[m + 8][k0    ];
                al[mt][2] = *(const uint32_t*)&sAl[m    ][k0 + 8];
                al[mt][3] = *(const uint32_t*)&sAl[m + 8][k0 + 8];
            }
            #pragma unroll
            for (int nt = 0; nt < 8; nt++) {
                int n = wn + nt * 8 + (lane >> 2);
                uint32_t bh0 = *(const uint32_t*)&sBh[n][k0    ];
                uint32_t bh1 = *(const uint32_t*)&sBh[n][k0 + 8];
                uint32_t bl0 = *(const uint32_t*)&sBl[n][k0    ];
                uint32_t bl1 = *(const uint32_t*)&sBl[n][k0 + 8];
                #pragma unroll
                for (int mt = 0; mt < 2; mt++) {
                    MMA16816(acc[mt][nt], ah[mt], bh0, bh1);
                    MMA16816(acc[mt][nt], ah[mt], bl0, bl1);
                    MMA16816(acc[mt][nt], al[mt], bh0, bh1);
                }
            }
        }
        __syncthreads();
    }

    // --- epilogue: bias (+relu), guarded N store ---
    const float* bias = ball + layer * NDIM;
    #pragma unroll
    for (int mt = 0; mt < 2; mt++) {
        #pragma unroll
        for (int hrow = 0; hrow < 2; hrow++) {
            int row = m0 + wm + mt * 16 + (lane >> 2) + hrow * 8;
            float* cp = C + (size_t)row * NDIM;
            #pragma unroll
            for (int nt = 0; nt < 8; nt++) {
                int col = n0 + wn + nt * 8 + (lane & 3) * 2;
                if (col < NDIM) {
                    float v0 = acc[mt][nt][hrow * 2 + 0] + __ldg(bias + col);
                    float v1 = acc[mt][nt][hrow * 2 + 1] + __ldg(bias + col + 1);
                    if (FIRST) { v0 = fmaxf(v0, 0.f); v1 = fmaxf(v1, 0.f); }
                    float2 st; st.x = v0; st.y = v1;
                    *(float2*)(cp + col) = st;
                }
            }
        }
    }
}

// ---------------------------------------------------------------------------
// BatchNorm, deterministic
// ---------------------------------------------------------------------------
__global__ void bn_part_kernel() {
    int c = threadIdx.x;
    if (c >= EMB) return;
    int r0   = blockIdx.x * 128;
    int rend = min(r0 + 128, N_NODES);
    float s = 0.f, q = 0.f;
    for (int r = r0; r < rend; r++) {
        float v = g_agg[r * EMB + c];
        s += v;
        q += v * v;
    }
    g_part[blockIdx.x * 2 * EMB + c]       = s;
    g_part[blockIdx.x * 2 * EMB + EMB + c] = q;
}
__global__ void bn_final_kernel(const float* __restrict__ gamma,
                                const float* __restrict__ beta, int layer) {
    int c = threadIdx.x;
    if (c >= EMB) return;
    float s = 0.f, q = 0.f;
    for (int b = 0; b < NCHUNK; b++) {
        s += g_part[b * 2 * EMB + c];
        q += g_part[b * 2 * EMB + EMB + c];
    }
    const float inv_n = 1.0f / (float)N_NODES;
    float mean = s * inv_n;
    float var  = q * inv_n - mean * mean;
    float sc = gamma[layer * EMB + c] * rsqrtf(var + 1e-5f);
    float sh = beta[layer * EMB + c] - mean * sc;
    g_stats[c]       = sc;
    g_stats[EMB + c] = sh;
}
__global__ void bn_apply_kernel(float* __restrict__ dst, int do_relu) {
    int idx = blockIdx.x * blockDim.x + threadIdx.x;
    if (idx >= N_NODES * 75) return;
    int c = (idx % 75) * 4;
    float4 v = ((const float4*)g_agg)[idx];
    float r0 = v.x * g_stats[c + 0] + g_stats[EMB + c + 0];
    float r1 = v.y * g_stats[c + 1] + g_stats[EMB + c + 1];
    float r2 = v.z * g_stats[c + 2] + g_stats[EMB + c + 2];
    float r3 = v.w * g_stats[c + 3] + g_stats[EMB + c + 3];
    if (do_relu) {
        r0 = fmaxf(r0, 0.f); r1 = fmaxf(r1, 0.f);
        r2 = fmaxf(r2, 0.f); r3 = fmaxf(r3, 0.f);
    }
    float* o = dst ? dst : g_h;
    ((float4*)o)[idx] = make_float4(r0, r1, r2, r3);
}

// ---------------------------------------------------------------------------
extern "C" void kernel_launch(void* const* d_in, const int* in_sizes, int n_in,
                              void* d_out, int out_size) {
    const int*   x     = (const int*)d_in[0];
    const int*   ei    = (const int*)d_in[1];
    const int*   ea    = (const int*)d_in[2];
    const float* xemb  = (const float*)d_in[3];
    const float* eemb  = (const float*)d_in[4];
    const float* W1    = (const float*)d_in[5];
    const float* b1    = (const float*)d_in[6];
    const float* W2    = (const float*)d_in[7];
    const float* b2    = (const float*)d_in[8];
    const float* gamma = (const float*)d_in[9];
    const float* beta  = (const float*)d_in[10];
    float* out = (float*)d_out;

    node_emb_kernel<<<(N_NODES * 75 + 255) / 256, 256>>>(x, xemb);
    prep_w1_kernel<<<(NLAYER * NP1 * KP1 + 255) / 256, 256>>>(W1);
    prep_w2_kernel<<<(NLAYER * NP2 * KP2 + 255) / 256, 256>>>(W2);

    // CSR build (deterministic)
    reset_kernel<<<(N_NODES + 255) / 256, 256>>>();
    combo_hist_kernel<<<(N_EDGES + 255) / 256, 256>>>(ei, ea);
    scan1_kernel<<<NBLK256, 256>>>();
    scan2_kernel<<<1, 256>>>();
    scan3_kernel<<<NBLK256, 256>>>();
    fill_kernel<<<(N_EDGES + 255) / 256, 256>>>(ei);
    sort_kernel<<<(N_NODES + 255) / 256, 256>>>();

    for (int layer = 0; layer < NLAYER; layer++) {
        gather_kernel<<<(M_PAD * 32 + 255) / 256, 256>>>(ei, eemb, layer);
        mma_gemm_kernel<true ><<<dim3(M_PAD / 128, NP1 / 128), 256>>>(b1, layer);
        mma_gemm_kernel<false><<<dim3(M_PAD / 128, NP2 / 128), 256>>>(b2, layer);
        bn_part_kernel<<<NCHUNK, 320>>>();
        bn_final_kernel<<<1, 320>>>(gamma, beta, layer);
        bn_apply_kernel<<<(N_NODES * 75 + 255) / 256, 256>>>(
            layer == NLAYER - 1 ? out : nullptr, layer != NLAYER - 1 ? 1 : 0);
    }
}

// round 6
// speedup vs baseline: 3.2552x; 1.1162x over previous
#include <cuda_runtime.h>
#include <cuda_bf16.h>
#include <cstdint>

// ---------------------------------------------------------------------------
// GIN encoder, deterministic. GEMMs: mma.sync bf16 hi/lo (3-MMA) with
// cp.async double-buffered pipeline; activations pre-split bf16 at producers.
// ---------------------------------------------------------------------------
#define N_NODES 50000
#define M_PAD   50048           // 391 * 128
#define EMB     300
#define EMB2    600
#define N_EDGES 800000
#define NLAYER  5
#define NCHUNK  391
#define NBLK256 196             // ceil(50000/256)

// GEMM1: K=300 (pad 320), N=600 (pad 640). GEMM2: K=600 (pad 608), N=300 (pad 384).
#define KP1 320
#define NP1 640
#define KP2 608
#define NP2 384

// Scratch state (allocation-free device globals; zero-initialized at load,
// pad regions are never written so they stay zero).
__device__ float g_h   [M_PAD * EMB];
__device__ float g_agg [M_PAD * EMB];                    // GEMM2 out / BN in
__device__ __align__(16) __nv_bfloat16 g_aggh[M_PAD * KP1];   // gather out hi
__device__ __align__(16) __nv_bfloat16 g_aggl[M_PAD * KP1];   // gather out lo
__device__ __align__(16) __nv_bfloat16 g_hidh[M_PAD * KP2];   // GEMM1 out hi
__device__ __align__(16) __nv_bfloat16 g_hidl[M_PAD * KP2];   // GEMM1 out lo
__device__ float g_stats[2 * EMB];
__device__ float g_part [NCHUNK * 2 * EMB];
__device__ int   g_deg [N_NODES];
__device__ int   g_cur [N_NODES];
__device__ int   g_cnt [N_NODES * 9];
__device__ int   g_off [N_NODES + 1];
__device__ int   g_src [N_EDGES];                        // CSR payload: src ids
__device__ int   g_bsum[256];
// pre-transposed, padded, bf16-split weights: [layer][NPAD][KPAD]
__device__ __align__(16) __nv_bfloat16 g_w1h[NLAYER * NP1 * KP1];
__device__ __align__(16) __nv_bfloat16 g_w1l[NLAYER * NP1 * KP1];
__device__ __align__(16) __nv_bfloat16 g_w2h[NLAYER * NP2 * KP2];
__device__ __align__(16) __nv_bfloat16 g_w2l[NLAYER * NP2 * KP2];

#define MMA16816(d, a, b0, b1)                                                \
    asm volatile("mma.sync.aligned.m16n8k16.row.col.f32.bf16.bf16.f32 "       \
        "{%0,%1,%2,%3}, {%4,%5,%6,%7}, {%8,%9}, {%0,%1,%2,%3};"               \
        : "+f"((d)[0]), "+f"((d)[1]), "+f"((d)[2]), "+f"((d)[3])              \
        : "r"((a)[0]), "r"((a)[1]), "r"((a)[2]), "r"((a)[3]),                 \
          "r"(b0), "r"(b1))

__device__ __forceinline__ void cpa16(uint32_t dst, const void* src) {
    asm volatile("cp.async.cg.shared.global [%0], [%1], 16;" :: "r"(dst), "l"(src));
}
#define CPA_COMMIT() asm volatile("cp.async.commit_group;" ::: "memory")
#define CPA_WAIT(n)  asm volatile("cp.async.wait_group %0;" :: "n"(n) : "memory")

__device__ __forceinline__ uint32_t smem_u32(const void* p) {
    uint32_t a;
    asm("{ .reg .u64 t; cvta.to.shared.u64 t, %1; cvt.u32.u64 %0, t; }" : "=r"(a) : "l"(p));
    return a;
}
// pack two floats to bf16x2 (lo = element 0)
__device__ __forceinline__ uint32_t packbf(float lo, float hi) {
    uint32_t r;
    asm("cvt.rn.bf16x2.f32 %0, %1, %2;" : "=r"(r) : "f"(hi), "f"(lo));
    return r;
}
__device__ __forceinline__ void split2(float x, float y, uint32_t& hi, uint32_t& lo) {
    __nv_bfloat16 hx = __float2bfloat16(x);
    __nv_bfloat16 hy = __float2bfloat16(y);
    hi = packbf(__bfloat16_as_ushort(hx) | 0u, 0.f), hi = 0;  // placeholder, replaced below
    float fx = __bfloat162float(hx), fy = __bfloat162float(hy);
    hi = ((uint32_t)__bfloat16_as_ushort(hy) << 16) | __bfloat16_as_ushort(hx);
    lo = packbf(x - fx, y - fy);
}

// ---------------------------------------------------------------------------
// h[i] = x_emb[x[i,0]] + x_emb[x[i,1]]
// ---------------------------------------------------------------------------
__global__ void node_emb_kernel(const int* __restrict__ x,
                                const float* __restrict__ xemb) {
    int idx = blockIdx.x * blockDim.x + threadIdx.x;
    if (idx >= N_NODES * 75) return;
    int row = idx / 75;
    int c4  = idx - row * 75;
    int a = x[2 * row];
    int b = x[2 * row + 1];
    float4 va = ((const float4*)(xemb + a * EMB))[c4];
    float4 vb = ((const float4*)(xemb + b * EMB))[c4];
    va.x += vb.x; va.y += vb.y; va.z += vb.z; va.w += vb.w;
    ((float4*)g_h)[idx] = va;
}

// ---------------------------------------------------------------------------
// Weight prep: transpose to [N][K], zero-pad, bf16 hi/lo split.
// ---------------------------------------------------------------------------
__global__ void prep_w1_kernel(const float* __restrict__ W1) {
    int idx = blockIdx.x * blockDim.x + threadIdx.x;
    if (idx >= NLAYER * NP1 * KP1) return;
    int layer = idx / (NP1 * KP1);
    int rem = idx - layer * NP1 * KP1;
    int n = rem / KP1, k = rem - n * KP1;
    float v = (n < EMB2 && k < EMB) ? W1[layer * EMB * EMB2 + k * EMB2 + n] : 0.f;
    __nv_bfloat16 h = __float2bfloat16(v);
    g_w1h[idx] = h;
    g_w1l[idx] = __float2bfloat16(v - __bfloat162float(h));
}
__global__ void prep_w2_kernel(const float* __restrict__ W2) {
    int idx = blockIdx.x * blockDim.x + threadIdx.x;
    if (idx >= NLAYER * NP2 * KP2) return;
    int layer = idx / (NP2 * KP2);
    int rem = idx - layer * NP2 * KP2;
    int n = rem / KP2, k = rem - n * KP2;
    float v = (n < EMB && k < EMB2) ? W2[layer * EMB2 * EMB + k * EMB + n] : 0.f;
    __nv_bfloat16 h = __float2bfloat16(v);
    g_w2h[idx] = h;
    g_w2l[idx] = __float2bfloat16(v - __bfloat162float(h));
}

// ---------------------------------------------------------------------------
// CSR build. Integer atomics only (deterministic); payload = src, sorted.
// ---------------------------------------------------------------------------
__global__ void reset_kernel() {
    int i = blockIdx.x * blockDim.x + threadIdx.x;
    if (i < N_NODES) {
        g_deg[i] = 0; g_cur[i] = 0;
        #pragma unroll
        for (int c = 0; c < 9; c++) g_cnt[i * 9 + c] = 0;
    }
}
__global__ void hist_kernel(const int* __restrict__ ei,
                            const int* __restrict__ ea) {
    int e = blockIdx.x * blockDim.x + threadIdx.x;
    if (e >= N_EDGES) return;
    int dst = ei[N_EDGES + e];
    int c = ea[2 * e] * 3 + ea[2 * e + 1];
    atomicAdd(&g_deg[dst], 1);
    atomicAdd(&g_cnt[dst * 9 + c], 1);
}
__global__ void scan1_kernel() {
    __shared__ int s[256];
    int tid = threadIdx.x;
    int i = blockIdx.x * 256 + tid;
    s[tid] = (i < N_NODES) ? g_deg[i] : 0;
    __syncthreads();
    #pragma unroll
    for (int d = 1; d < 256; d <<= 1) {
        int t = (tid >= d) ? s[tid - d] : 0;
        __syncthreads();
        s[tid] += t;
        __syncthreads();
    }
    if (i < N_NODES) g_off[i + 1] = s[tid];
    if (tid == 255) g_bsum[blockIdx.x] = s[255];
}
__global__ void scan2_kernel() {
    __shared__ int s[256];
    int tid = threadIdx.x;
    s[tid] = (tid < NBLK256) ? g_bsum[tid] : 0;
    __syncthreads();
    #pragma unroll
    for (int d = 1; d < 256; d <<= 1) {
        int t = (tid >= d) ? s[tid - d] : 0;
        __syncthreads();
        s[tid] += t;
        __syncthreads();
    }
    g_bsum[tid] = s[tid];
}
__global__ void scan3_kernel() {
    int i = blockIdx.x * 256 + threadIdx.x;
    if (i < N_NODES && blockIdx.x > 0) g_off[i + 1] += g_bsum[blockIdx.x - 1];
    if (i == 0) g_off[0] = 0;
}
__global__ void fill_kernel(const int* __restrict__ ei) {
    int e = blockIdx.x * blockDim.x + threadIdx.x;
    if (e >= N_EDGES) return;
    int dst = ei[N_EDGES + e];
    int slot = atomicAdd(&g_cur[dst], 1);
    g_src[g_off[dst] + slot] = ei[e];
}
__global__ void sort_kernel() {          // sort src values; equal keys commute
    int n = blockIdx.x * blockDim.x + threadIdx.x;
    if (n >= N_NODES) return;
    int a = g_off[n], b = g_off[n + 1];
    for (int i = a + 1; i < b; i++) {
        int key = g_src[i];
        int j = i - 1;
        while (j >= a && g_src[j] > key) { g_src[j + 1] = g_src[j]; j--; }
        g_src[j + 1] = key;
    }
}

// ---------------------------------------------------------------------------
// Gather: one warp per node, sorted-src order -> deterministic.
// agg[n] = h[n] + selfc + sum_c cnt[n][c]*comb[c] + sum_src h[src]
// Output written as bf16 hi/lo, stride KP1 (pad cols stay zero-initialized).
// ---------------------------------------------------------------------------
__global__ void gather_kernel(const float* __restrict__ eemb, int layer) {
    __shared__ __align__(16) float comb[9 * EMB];
    __shared__ __align__(16) float selfc[EMB];
    const float* emb = eemb + layer * 6 * EMB;
    for (int i = threadIdx.x; i < 9 * EMB; i += blockDim.x) {
        int c = i / EMB;
        int d = i - c * EMB;
        comb[i] = emb[(c / 3) * EMB + d] + emb[(c % 3) * EMB + d];
    }
    for (int i = threadIdx.x; i < EMB; i += blockDim.x)
        selfc[i] = emb[4 * EMB + i] + emb[0 * EMB + i];
    __syncthreads();

    int lane = threadIdx.x & 31;
    int node = (blockIdx.x * blockDim.x + threadIdx.x) >> 5;
    if (node >= N_NODES) return;    // pad rows stay zero-initialized

    float4 acc[3];
    #pragma unroll
    for (int k = 0; k < 3; k++) acc[k] = make_float4(0.f, 0.f, 0.f, 0.f);

    const float4* hn = (const float4*)(g_h + node * EMB);
    const float4* sc = (const float4*)selfc;
    #pragma unroll
    for (int k = 0; k < 3; k++) {
        int j = lane + k * 32;
        if (j < 75) {
            float4 a = hn[j], b = sc[j];
            acc[k].x = a.x + b.x; acc[k].y = a.y + b.y;
            acc[k].z = a.z + b.z; acc[k].w = a.w + b.w;
        }
    }
    // combo contribution via counts (layer-invariant counts, per-layer comb)
    const int* cnt = g_cnt + node * 9;
    #pragma unroll
    for (int c = 0; c < 9; c++) {
        float cf = (float)cnt[c];
        if (cnt[c] == 0) continue;
        const float4* cb = (const float4*)(comb + c * EMB);
        #pragma unroll
        for (int k = 0; k < 3; k++) {
            int j = lane + k * 32;
            if (j < 75) {
                float4 b = cb[j];
                acc[k].x += cf * b.x; acc[k].y += cf * b.y;
                acc[k].z += cf * b.z; acc[k].w += cf * b.w;
            }
        }
    }
    // neighbor sum, 2-way unrolled for MLP
    int beg = g_off[node], end = g_off[node + 1];
    int idx = beg;
    for (; idx + 1 < end; idx += 2) {
        int s0 = g_src[idx], s1 = g_src[idx + 1];
        const float4* h0 = (const float4*)(g_h + s0 * EMB);
        const float4* h1 = (const float4*)(g_h + s1 * EMB);
        #pragma unroll
        for (int k = 0; k < 3; k++) {
            int j = lane + k * 32;
            if (j < 75) {
                float4 a = h0[j], b = h1[j];
                acc[k].x += a.x; acc[k].y += a.y; acc[k].z += a.z; acc[k].w += a.w;
                acc[k].x += b.x; acc[k].y += b.y; acc[k].z += b.z; acc[k].w += b.w;
            }
        }
    }
    if (idx < end) {
        int s0 = g_src[idx];
        const float4* h0 = (const float4*)(g_h + s0 * EMB);
        #pragma unroll
        for (int k = 0; k < 3; k++) {
            int j = lane + k * 32;
            if (j < 75) {
                float4 a = h0[j];
                acc[k].x += a.x; acc[k].y += a.y; acc[k].z += a.z; acc[k].w += a.w;
            }
        }
    }
    // write bf16 hi/lo, stride KP1
    #pragma unroll
    for (int k = 0; k < 3; k++) {
        int j = lane + k * 32;
        if (j < 75) {
            uint32_t h01, l01, h23, l23;
            split2(acc[k].x, acc[k].y, h01, l01);
            split2(acc[k].z, acc[k].w, h23, l23);
            uint2 hv; hv.x = h01; hv.y = h23;
            uint2 lv; lv.x = l01; lv.y = l23;
            *(uint2*)(g_aggh + (size_t)node * KP1 + j * 4) = hv;
            *(uint2*)(g_aggl + (size_t)node * KP1 + j * 4) = lv;
        }
    }
}

// ---------------------------------------------------------------------------
// Pipelined bf16x3 GEMM with cp.async double buffering.
// FIRST:  A=aggh/aggl (KP1), B=w1 (NP1), out=hidh/hidl bf16 (stride KP2), relu
// !FIRST: A=hidh/hidl (KP2), B=w2 (NP2), out=g_agg fp32 (stride EMB)
// 128x128 CTA tile, BK=32, 8 warps (32x64 warp tile), 256 threads.
// Dynamic smem: 2 stages x 4 arrays x [128][40] bf16 = 81920 B.
// ---------------------------------------------------------------------------
#define STG_BYTES 40960
#define OFF_AH 0
#define OFF_AL 10240
#define OFF_BH 20480
#define OFF_BL 30720
#define GEMM_SMEM (2 * STG_BYTES)

template <bool FIRST>
__global__ void __launch_bounds__(256, 2) mma_gemm_kernel(const float* __restrict__ ball,
                                                          int layer) {
    constexpr int NDIM = FIRST ? EMB2 : EMB;
    constexpr int KPAD = FIRST ? KP1 : KP2;
    constexpr int NPAD = FIRST ? NP1 : NP2;
    constexpr int NKB  = KPAD / 32;

    const __nv_bfloat16* __restrict__ Ah = FIRST ? g_aggh : g_hidh;
    const __nv_bfloat16* __restrict__ Al = FIRST ? g_aggl : g_hidl;
    const __nv_bfloat16* __restrict__ Bh = FIRST ? g_w1h : g_w2h;
    const __nv_bfloat16* __restrict__ Bl = FIRST ? g_w1l : g_w2l;

    extern __shared__ __align__(16) char sm[];
    uint32_t sb = smem_u32(sm);

    int tid  = threadIdx.x;
    int lane = tid & 31;
    int wid  = tid >> 5;
    int wm   = (wid & 3) * 32;
    int wn   = (wid >> 2) * 64;
    int m0   = blockIdx.x * 128;
    int n0   = blockIdx.y * 128;

    float acc[2][8][4];
    #pragma unroll
    for (int mt = 0; mt < 2; mt++)
        #pragma unroll
        for (int nt = 0; nt < 8; nt++)
            #pragma unroll
            for (int q = 0; q < 4; q++) acc[mt][nt][q] = 0.f;

    const size_t bbase = ((size_t)layer * NPAD + n0) * KPAD;

    // issue one stage of cp.async (A hi/lo + B hi/lo, 128x32 bf16 each)
    auto issue = [&](int kb, int st) {
        uint32_t base = sb + st * STG_BYTES;
        #pragma unroll
        for (int i = 0; i < 2; i++) {
            int v = tid + i * 256;            // 0..511
            int r = v >> 2;                   // 0..127
            int c = v & 3;                    // 16B chunk
            uint32_t so = r * 80 + c * 16;
            size_t ga = (size_t)(m0 + r) * KPAD + kb * 32 + c * 8;
            cpa16(base + OFF_AH + so, Ah + ga);
            cpa16(base + OFF_AL + so, Al + ga);
            size_t gb = bbase + (size_t)r * KPAD + kb * 32 + c * 8;
            cpa16(base + OFF_BH + so, Bh + gb);
            cpa16(base + OFF_BL + so, Bl + gb);
        }
        CPA_COMMIT();
    };

    issue(0, 0);

    for (int kb = 0; kb < NKB; kb++) {
        int st = kb & 1;
        if (kb + 1 < NKB) { issue(kb + 1, st ^ 1); CPA_WAIT(1); }
        else              { CPA_WAIT(0); }
        __syncthreads();

        char* base = sm + st * STG_BYTES;
        typedef __nv_bfloat16 (*T40)[40];
        T40 pAh = (T40)(base + OFF_AH);
        T40 pAl = (T40)(base + OFF_AL);
        T40 pBh = (T40)(base + OFF_BH);
        T40 pBl = (T40)(base + OFF_BL);

        #pragma unroll
        for (int c = 0; c < 2; c++) {
            int k0 = c * 16 + (lane & 3) * 2;
            int ma = wm + (lane >> 2);
            uint32_t ah[2][4], al[2][4];
            #pragma unroll
            for (int mt = 0; mt < 2; mt++) {
                int m = ma + mt * 16;
                ah[mt][0] = *(const uint32_t*)&pAh[m    ][k0    ];
                ah[mt][1] = *(const uint32_t*)&pAh[m + 8][k0    ];
                ah[mt][2] = *(const uint32_t*)&pAh[m    ][k0 + 8];
                ah[mt][3] = *(const uint32_t*)&pAh[m + 8][k0 + 8];
                al[mt][0] = *(const uint32_t*)&pAl[m    ][k0    ];
                al[mt][1] = *(const uint32_t*)&pAl[m + 8][k0    ];
                al[mt][2] = *(const uint32_t*)&pAl[m    ][k0 + 8];
                al[mt][3] = *(const uint32_t*)&pAl[m + 8][k0 + 8];
            }
            #pragma unroll
            for (int nt = 0; nt < 8; nt++) {
                int n = wn + nt * 8 + (lane >> 2);
                uint32_t bh0 = *(const uint32_t*)&pBh[n][k0    ];
                uint32_t bh1 = *(const uint32_t*)&pBh[n][k0 + 8];
                uint32_t bl0 = *(const uint32_t*)&pBl[n][k0    ];
                uint32_t bl1 = *(const uint32_t*)&pBl[n][k0 + 8];
                #pragma unroll
                for (int mt = 0; mt < 2; mt++) {
                    MMA16816(acc[mt][nt], ah[mt], bh0, bh1);
                    MMA16816(acc[mt][nt], ah[mt], bl0, bl1);
                    MMA16816(acc[mt][nt], al[mt], bh0, bh1);
                }
            }
        }
        __syncthreads();    // all warps done with stage st before it is refilled
    }

    // --- epilogue ---
    const float* bias = ball + layer * NDIM;
    #pragma unroll
    for (int mt = 0; mt < 2; mt++) {
        #pragma unroll
        for (int hrow = 0; hrow < 2; hrow++) {
            int row = m0 + wm + mt * 16 + (lane >> 2) + hrow * 8;
            #pragma unroll
            for (int nt = 0; nt < 8; nt++) {
                int col = n0 + wn + nt * 8 + (lane & 3) * 2;
                if (col < NDIM) {
                    float v0 = acc[mt][nt][hrow * 2 + 0] + __ldg(bias + col);
                    float v1 = acc[mt][nt][hrow * 2 + 1] + __ldg(bias + col + 1);
                    if (FIRST) {
                        v0 = fmaxf(v0, 0.f); v1 = fmaxf(v1, 0.f);
                        uint32_t hi, lo;
                        split2(v0, v1, hi, lo);
                        *(uint32_t*)(g_hidh + (size_t)row * KP2 + col) = hi;
                        *(uint32_t*)(g_hidl + (size_t)row * KP2 + col) = lo;
                    } else {
                        float2 st; st.x = v0; st.y = v1;
                        *(float2*)(g_agg + (size_t)row * EMB + col) = st;
                    }
                }
            }
        }
    }
}

// ---------------------------------------------------------------------------
// BatchNorm, deterministic
// ---------------------------------------------------------------------------
__global__ void bn_part_kernel() {
    int c = threadIdx.x;
    if (c >= EMB) return;
    int r0   = blockIdx.x * 128;
    int rend = min(r0 + 128, N_NODES);
    float s = 0.f, q = 0.f;
    for (int r = r0; r < rend; r++) {
        float v = g_agg[r * EMB + c];
        s += v;
        q += v * v;
    }
    g_part[blockIdx.x * 2 * EMB + c]       = s;
    g_part[blockIdx.x * 2 * EMB + EMB + c] = q;
}
__global__ void bn_final_kernel(const float* __restrict__ gamma,
                                const float* __restrict__ beta, int layer) {
    int c = threadIdx.x;
    if (c >= EMB) return;
    float s = 0.f, q = 0.f;
    for (int b = 0; b < NCHUNK; b++) {
        s += g_part[b * 2 * EMB + c];
        q += g_part[b * 2 * EMB + EMB + c];
    }
    const float inv_n = 1.0f / (float)N_NODES;
    float mean = s * inv_n;
    float var  = q * inv_n - mean * mean;
    float sc = gamma[layer * EMB + c] * rsqrtf(var + 1e-5f);
    float sh = beta[layer * EMB + c] - mean * sc;
    g_stats[c]       = sc;
    g_stats[EMB + c] = sh;
}
__global__ void bn_apply_kernel(float* __restrict__ dst, int do_relu) {
    int idx = blockIdx.x * blockDim.x + threadIdx.x;
    if (idx >= N_NODES * 75) return;
    int c = (idx % 75) * 4;
    float4 v = ((const float4*)g_agg)[idx];
    float r0 = v.x * g_stats[c + 0] + g_stats[EMB + c + 0];
    float r1 = v.y * g_stats[c + 1] + g_stats[EMB + c + 1];
    float r2 = v.z * g_stats[c + 2] + g_stats[EMB + c + 2];
    float r3 = v.w * g_stats[c + 3] + g_stats[EMB + c + 3];
    if (do_relu) {
        r0 = fmaxf(r0, 0.f); r1 = fmaxf(r1, 0.f);
        r2 = fmaxf(r2, 0.f); r3 = fmaxf(r3, 0.f);
    }
    float* o = dst ? dst : g_h;
    ((float4*)o)[idx] = make_float4(r0, r1, r2, r3);
}

// ---------------------------------------------------------------------------
extern "C" void kernel_launch(void* const* d_in, const int* in_sizes, int n_in,
                              void* d_out, int out_size) {
    const int*   x     = (const int*)d_in[0];
    const int*   ei    = (const int*)d_in[1];
    const int*   ea    = (const int*)d_in[2];
    const float* xemb  = (const float*)d_in[3];
    const float* eemb  = (const float*)d_in[4];
    const float* W1    = (const float*)d_in[5];
    const float* b1    = (const float*)d_in[6];
    const float* W2    = (const float*)d_in[7];
    const float* b2    = (const float*)d_in[8];
    const float* gamma = (const float*)d_in[9];
    const float* beta  = (const float*)d_in[10];
    float* out = (float*)d_out;

    cudaFuncSetAttribute(mma_gemm_kernel<true>,
                         cudaFuncAttributeMaxDynamicSharedMemorySize, GEMM_SMEM);
    cudaFuncSetAttribute(mma_gemm_kernel<false>,
                         cudaFuncAttributeMaxDynamicSharedMemorySize, GEMM_SMEM);

    node_emb_kernel<<<(N_NODES * 75 + 255) / 256, 256>>>(x, xemb);
    prep_w1_kernel<<<(NLAYER * NP1 * KP1 + 255) / 256, 256>>>(W1);
    prep_w2_kernel<<<(NLAYER * NP2 * KP2 + 255) / 256, 256>>>(W2);

    // CSR build (deterministic)
    reset_kernel<<<(N_NODES + 255) / 256, 256>>>();
    hist_kernel<<<(N_EDGES + 255) / 256, 256>>>(ei, ea);
    scan1_kernel<<<NBLK256, 256>>>();
    scan2_kernel<<<1, 256>>>();
    scan3_kernel<<<NBLK256, 256>>>();
    fill_kernel<<<(N_EDGES + 255) / 256, 256>>>(ei);
    sort_kernel<<<(N_NODES + 255) / 256, 256>>>();

    for (int layer = 0; layer < NLAYER; layer++) {
        gather_kernel<<<(N_NODES * 32 + 255) / 256, 256>>>(eemb, layer);
        mma_gemm_kernel<true ><<<dim3(M_PAD / 128, NP1 / 128), 256, GEMM_SMEM>>>(b1, layer);
        mma_gemm_kernel<false><<<dim3(M_PAD / 128, NP2 / 128), 256, GEMM_SMEM>>>(b2, layer);
        bn_part_kernel<<<NCHUNK, 320>>>();
        bn_final_kernel<<<1, 320>>>(gamma, beta, layer);
        bn_apply_kernel<<<(N_NODES * 75 + 255) / 256, 256>>>(
            layer == NLAYER - 1 ? out : nullptr, layer != NLAYER - 1 ? 1 : 0);
    }
}

// round 7
// speedup vs baseline: 3.4205x; 1.0508x over previous
#include <cuda_runtime.h>
#include <cuda_bf16.h>
#include <cstdint>

// ---------------------------------------------------------------------------
// GIN encoder, deterministic. GEMMs: mma.sync bf16 hi/lo (3-MMA), cp.async
// double-buffered, ldmatrix fragment loads. BN fused into gather.
// ---------------------------------------------------------------------------
#define N_NODES 50000
#define M_PAD   50048           // 391 * 128
#define EMB     300
#define EMB2    600
#define N_EDGES 800000
#define NLAYER  5
#define NCHUNK  391
#define NBLK256 196             // ceil(50000/256)

// GEMM1: K=300 (pad 320), N=600 (pad 640). GEMM2: K=600 (pad 608), N=300 (pad 384).
#define KP1 320
#define NP1 640
#define KP2 608
#define NP2 384

// Scratch (device globals, zero-initialized; pad regions never written).
__device__ float g_h   [M_PAD * EMB];                        // layer-0 node emb
__device__ float g_agg [M_PAD * EMB];                        // GEMM2 out / BN in
__device__ __align__(16) __nv_bfloat16 g_aggh[M_PAD * KP1];  // gather out hi
__device__ __align__(16) __nv_bfloat16 g_aggl[M_PAD * KP1];  // gather out lo
__device__ __align__(16) __nv_bfloat16 g_hidh[M_PAD * KP2];  // GEMM1 out hi
__device__ __align__(16) __nv_bfloat16 g_hidl[M_PAD * KP2];  // GEMM1 out lo
__device__ float g_stats[2 * EMB];
__device__ float g_part [NCHUNK * 2 * EMB];
__device__ int   g_deg [N_NODES];
__device__ int   g_cur [N_NODES];
__device__ int   g_cnt [N_NODES * 9];
__device__ int   g_off [N_NODES + 1];
__device__ int   g_src [N_EDGES];
__device__ int   g_bsum[256];
// pre-transposed, padded, bf16-split weights: [layer][NPAD][KPAD]
__device__ __align__(16) __nv_bfloat16 g_w1h[NLAYER * NP1 * KP1];
__device__ __align__(16) __nv_bfloat16 g_w1l[NLAYER * NP1 * KP1];
__device__ __align__(16) __nv_bfloat16 g_w2h[NLAYER * NP2 * KP2];
__device__ __align__(16) __nv_bfloat16 g_w2l[NLAYER * NP2 * KP2];

#define MMA16816(d, a, b0, b1)                                                \
    asm volatile("mma.sync.aligned.m16n8k16.row.col.f32.bf16.bf16.f32 "       \
        "{%0,%1,%2,%3}, {%4,%5,%6,%7}, {%8,%9}, {%0,%1,%2,%3};"               \
        : "+f"((d)[0]), "+f"((d)[1]), "+f"((d)[2]), "+f"((d)[3])              \
        : "r"((a)[0]), "r"((a)[1]), "r"((a)[2]), "r"((a)[3]),                 \
          "r"(b0), "r"(b1))

#define LDSM_X4(r, addr)                                                      \
    asm volatile("ldmatrix.sync.aligned.m8n8.x4.shared.b16 {%0,%1,%2,%3}, [%4];" \
        : "=r"((r)[0]), "=r"((r)[1]), "=r"((r)[2]), "=r"((r)[3]) : "r"(addr))

__device__ __forceinline__ void cpa16(uint32_t dst, const void* src) {
    asm volatile("cp.async.cg.shared.global [%0], [%1], 16;" :: "r"(dst), "l"(src));
}
#define CPA_COMMIT() asm volatile("cp.async.commit_group;" ::: "memory")
#define CPA_WAIT(n)  asm volatile("cp.async.wait_group %0;" :: "n"(n) : "memory")

__device__ __forceinline__ uint32_t smem_u32(const void* p) {
    uint32_t a;
    asm("{ .reg .u64 t; cvta.to.shared.u64 t, %1; cvt.u32.u64 %0, t; }" : "=r"(a) : "l"(p));
    return a;
}
__device__ __forceinline__ uint32_t packbf(float lo, float hi) {
    uint32_t r;
    asm("cvt.rn.bf16x2.f32 %0, %1, %2;" : "=r"(r) : "f"(hi), "f"(lo));
    return r;
}
__device__ __forceinline__ void split2(float x, float y, uint32_t& hi, uint32_t& lo) {
    __nv_bfloat16 hx = __float2bfloat16(x), hy = __float2bfloat16(y);
    hi = ((uint32_t)__bfloat16_as_ushort(hy) << 16) | __bfloat16_as_ushort(hx);
    lo = packbf(x - __bfloat162float(hx), y - __bfloat162float(hy));
}

// ---------------------------------------------------------------------------
__global__ void node_emb_kernel(const int* __restrict__ x,
                                const float* __restrict__ xemb) {
    int idx = blockIdx.x * blockDim.x + threadIdx.x;
    if (idx >= N_NODES * 75) return;
    int row = idx / 75;
    int c4  = idx - row * 75;
    int a = x[2 * row];
    int b = x[2 * row + 1];
    float4 va = ((const float4*)(xemb + a * EMB))[c4];
    float4 vb = ((const float4*)(xemb + b * EMB))[c4];
    va.x += vb.x; va.y += vb.y; va.z += vb.z; va.w += vb.w;
    ((float4*)g_h)[idx] = va;
}

// ---------------------------------------------------------------------------
__global__ void prep_w1_kernel(const float* __restrict__ W1) {
    int idx = blockIdx.x * blockDim.x + threadIdx.x;
    if (idx >= NLAYER * NP1 * KP1) return;
    int layer = idx / (NP1 * KP1);
    int rem = idx - layer * NP1 * KP1;
    int n = rem / KP1, k = rem - n * KP1;
    float v = (n < EMB2 && k < EMB) ? W1[layer * EMB * EMB2 + k * EMB2 + n] : 0.f;
    __nv_bfloat16 h = __float2bfloat16(v);
    g_w1h[idx] = h;
    g_w1l[idx] = __float2bfloat16(v - __bfloat162float(h));
}
__global__ void prep_w2_kernel(const float* __restrict__ W2) {
    int idx = blockIdx.x * blockDim.x + threadIdx.x;
    if (idx >= NLAYER * NP2 * KP2) return;
    int layer = idx / (NP2 * KP2);
    int rem = idx - layer * NP2 * KP2;
    int n = rem / KP2, k = rem - n * KP2;
    float v = (n < EMB && k < EMB2) ? W2[layer * EMB2 * EMB + k * EMB + n] : 0.f;
    __nv_bfloat16 h = __float2bfloat16(v);
    g_w2h[idx] = h;
    g_w2l[idx] = __float2bfloat16(v - __bfloat162float(h));
}

// ---------------------------------------------------------------------------
// CSR build (deterministic)
// ---------------------------------------------------------------------------
__global__ void reset_kernel() {
    int i = blockIdx.x * blockDim.x + threadIdx.x;
    if (i < N_NODES) {
        g_deg[i] = 0; g_cur[i] = 0;
        #pragma unroll
        for (int c = 0; c < 9; c++) g_cnt[i * 9 + c] = 0;
    }
}
__global__ void hist_kernel(const int* __restrict__ ei,
                            const int* __restrict__ ea) {
    int e = blockIdx.x * blockDim.x + threadIdx.x;
    if (e >= N_EDGES) return;
    int dst = ei[N_EDGES + e];
    int c = ea[2 * e] * 3 + ea[2 * e + 1];
    atomicAdd(&g_deg[dst], 1);
    atomicAdd(&g_cnt[dst * 9 + c], 1);
}
__global__ void scan1_kernel() {
    __shared__ int s[256];
    int tid = threadIdx.x;
    int i = blockIdx.x * 256 + tid;
    s[tid] = (i < N_NODES) ? g_deg[i] : 0;
    __syncthreads();
    #pragma unroll
    for (int d = 1; d < 256; d <<= 1) {
        int t = (tid >= d) ? s[tid - d] : 0;
        __syncthreads();
        s[tid] += t;
        __syncthreads();
    }
    if (i < N_NODES) g_off[i + 1] = s[tid];
    if (tid == 255) g_bsum[blockIdx.x] = s[255];
}
__global__ void scan2_kernel() {
    __shared__ int s[256];
    int tid = threadIdx.x;
    s[tid] = (tid < NBLK256) ? g_bsum[tid] : 0;
    __syncthreads();
    #pragma unroll
    for (int d = 1; d < 256; d <<= 1) {
        int t = (tid >= d) ? s[tid - d] : 0;
        __syncthreads();
        s[tid] += t;
        __syncthreads();
    }
    g_bsum[tid] = s[tid];
}
__global__ void scan3_kernel() {
    int i = blockIdx.x * 256 + threadIdx.x;
    if (i < N_NODES && blockIdx.x > 0) g_off[i + 1] += g_bsum[blockIdx.x - 1];
    if (i == 0) g_off[0] = 0;
}
__global__ void fill_kernel(const int* __restrict__ ei) {
    int e = blockIdx.x * blockDim.x + threadIdx.x;
    if (e >= N_EDGES) return;
    int dst = ei[N_EDGES + e];
    int slot = atomicAdd(&g_cur[dst], 1);
    g_src[g_off[dst] + slot] = ei[e];
}
__global__ void sort_kernel() {          // sort src values; equal keys commute
    int n = blockIdx.x * blockDim.x + threadIdx.x;
    if (n >= N_NODES) return;
    int a = g_off[n], b = g_off[n + 1];
    for (int i = a + 1; i < b; i++) {
        int key = g_src[i];
        int j = i - 1;
        while (j >= a && g_src[j] > key) { g_src[j + 1] = g_src[j]; j--; }
        g_src[j + 1] = key;
    }
}

// ---------------------------------------------------------------------------
// Gather (+fused BN/ReLU on the source values when BN=true).
// agg[n] = f(src[n]) + selfc + sum_c cnt[n][c]*comb[c] + sum_e f(src[e])
// where f(v) = BN ? relu(v*sc + sh) : v, per column. Deterministic: sorted
// edge order, f recomputed identically per read.
// ---------------------------------------------------------------------------
template <bool BN>
__global__ void gather_kernel(const float* __restrict__ srcdata,
                              const float* __restrict__ eemb, int layer) {
    __shared__ __align__(16) float comb[9 * EMB];
    __shared__ __align__(16) float selfc[EMB];
    __shared__ __align__(16) float scs[EMB];
    __shared__ __align__(16) float shs[EMB];
    const float* emb = eemb + layer * 6 * EMB;
    for (int i = threadIdx.x; i < 9 * EMB; i += blockDim.x) {
        int c = i / EMB;
        int d = i - c * EMB;
        comb[i] = emb[(c / 3) * EMB + d] + emb[(c % 3) * EMB + d];
    }
    for (int i = threadIdx.x; i < EMB; i += blockDim.x) {
        selfc[i] = emb[4 * EMB + i] + emb[0 * EMB + i];
        if (BN) { scs[i] = g_stats[i]; shs[i] = g_stats[EMB + i]; }
    }
    __syncthreads();

    int lane = threadIdx.x & 31;
    int node = (blockIdx.x * blockDim.x + threadIdx.x) >> 5;
    if (node >= N_NODES) return;

    // per-thread column positions j = lane + k*32 (k<3, j<75)
    float4 scv[3], shv[3];
    if (BN) {
        #pragma unroll
        for (int k = 0; k < 3; k++) {
            int j = lane + k * 32;
            if (j < 75) { scv[k] = ((const float4*)scs)[j]; shv[k] = ((const float4*)shs)[j]; }
        }
    }
    auto xf = [&](float4 v, int k) -> float4 {
        if (!BN) return v;
        float4 r;
        r.x = fmaxf(fmaf(v.x, scv[k].x, shv[k].x), 0.f);
        r.y = fmaxf(fmaf(v.y, scv[k].y, shv[k].y), 0.f);
        r.z = fmaxf(fmaf(v.z, scv[k].z, shv[k].z), 0.f);
        r.w = fmaxf(fmaf(v.w, scv[k].w, shv[k].w), 0.f);
        return r;
    };

    float4 acc[3];
    const float4* hn = (const float4*)(srcdata + (size_t)node * EMB);
    const float4* sc = (const float4*)selfc;
    #pragma unroll
    for (int k = 0; k < 3; k++) {
        int j = lane + k * 32;
        acc[k] = make_float4(0.f, 0.f, 0.f, 0.f);
        if (j < 75) {
            float4 a = xf(hn[j], k), b = sc[j];
            acc[k].x = a.x + b.x; acc[k].y = a.y + b.y;
            acc[k].z = a.z + b.z; acc[k].w = a.w + b.w;
        }
    }
    const int* cnt = g_cnt + node * 9;
    #pragma unroll
    for (int c = 0; c < 9; c++) {
        int cc = cnt[c];
        if (cc == 0) continue;
        float cf = (float)cc;
        const float4* cb = (const float4*)(comb + c * EMB);
        #pragma unroll
        for (int k = 0; k < 3; k++) {
            int j = lane + k * 32;
            if (j < 75) {
                float4 b = cb[j];
                acc[k].x += cf * b.x; acc[k].y += cf * b.y;
                acc[k].z += cf * b.z; acc[k].w += cf * b.w;
            }
        }
    }
    int beg = g_off[node], end = g_off[node + 1];
    int idx = beg;
    for (; idx + 1 < end; idx += 2) {
        int s0 = g_src[idx], s1 = g_src[idx + 1];
        const float4* h0 = (const float4*)(srcdata + (size_t)s0 * EMB);
        const float4* h1 = (const float4*)(srcdata + (size_t)s1 * EMB);
        #pragma unroll
        for (int k = 0; k < 3; k++) {
            int j = lane + k * 32;
            if (j < 75) {
                float4 a = xf(h0[j], k), b = xf(h1[j], k);
                acc[k].x += a.x + b.x; acc[k].y += a.y + b.y;
                acc[k].z += a.z + b.z; acc[k].w += a.w + b.w;
            }
        }
    }
    if (idx < end) {
        int s0 = g_src[idx];
        const float4* h0 = (const float4*)(srcdata + (size_t)s0 * EMB);
        #pragma unroll
        for (int k = 0; k < 3; k++) {
            int j = lane + k * 32;
            if (j < 75) {
                float4 a = xf(h0[j], k);
                acc[k].x += a.x; acc[k].y += a.y; acc[k].z += a.z; acc[k].w += a.w;
            }
        }
    }
    #pragma unroll
    for (int k = 0; k < 3; k++) {
        int j = lane + k * 32;
        if (j < 75) {
            uint32_t h01, l01, h23, l23;
            split2(acc[k].x, acc[k].y, h01, l01);
            split2(acc[k].z, acc[k].w, h23, l23);
            uint2 hv; hv.x = h01; hv.y = h23;
            uint2 lv; lv.x = l01; lv.y = l23;
            *(uint2*)(g_aggh + (size_t)node * KP1 + j * 4) = hv;
            *(uint2*)(g_aggl + (size_t)node * KP1 + j * 4) = lv;
        }
    }
}

// ---------------------------------------------------------------------------
// Pipelined bf16x3 GEMM: cp.async double buffer + ldmatrix fragment loads.
// 128x128 CTA tile, BK=32, 8 warps (32x64 warp tile), 256 threads.
// ---------------------------------------------------------------------------
#define STG_BYTES 40960
#define OFF_AH 0
#define OFF_AL 10240
#define OFF_BH 20480
#define OFF_BL 30720
#define GEMM_SMEM (2 * STG_BYTES)

template <bool FIRST>
__global__ void __launch_bounds__(256, 2) mma_gemm_kernel(const float* __restrict__ ball,
                                                          int layer) {
    constexpr int NDIM = FIRST ? EMB2 : EMB;
    constexpr int KPAD = FIRST ? KP1 : KP2;
    constexpr int NPAD = FIRST ? NP1 : NP2;
    constexpr int NKB  = KPAD / 32;

    const __nv_bfloat16* __restrict__ Ah = FIRST ? g_aggh : g_hidh;
    const __nv_bfloat16* __restrict__ Al = FIRST ? g_aggl : g_hidl;
    const __nv_bfloat16* __restrict__ Bh = FIRST ? g_w1h : g_w2h;
    const __nv_bfloat16* __restrict__ Bl = FIRST ? g_w1l : g_w2l;

    extern __shared__ __align__(16) char sm[];
    uint32_t sb = smem_u32(sm);

    int tid  = threadIdx.x;
    int lane = tid & 31;
    int wid  = tid >> 5;
    int wm   = (wid & 3) * 32;
    int wn   = (wid >> 2) * 64;
    int m0   = blockIdx.x * 128;
    int n0   = blockIdx.y * 128;

    // ldmatrix lane mapping: groups of 8 lanes provide 8 row addrs per matrix.
    int lg = lane >> 3, lj = lane & 7;
    int a_row = (lg & 1) * 8 + lj;    // A matrices: m0k0, m8k0, m0k8, m8k8
    int a_k8  = (lg >> 1) * 8;
    int b_row = (lg >> 1) * 8 + lj;   // B matrices: n0k0, n0k8, n8k0, n8k8
    int b_k8  = (lg & 1) * 8;

    float acc[2][8][4];
    #pragma unroll
    for (int mt = 0; mt < 2; mt++)
        #pragma unroll
        for (int nt = 0; nt < 8; nt++)
            #pragma unroll
            for (int q = 0; q < 4; q++) acc[mt][nt][q] = 0.f;

    const size_t bbase = ((size_t)layer * NPAD + n0) * KPAD;

    auto issue = [&](int kb, int st) {
        uint32_t base = sb + st * STG_BYTES;
        #pragma unroll
        for (int i = 0; i < 2; i++) {
            int v = tid + i * 256;
            int r = v >> 2;
            int c = v & 3;
            uint32_t so = r * 80 + c * 16;
            size_t ga = (size_t)(m0 + r) * KPAD + kb * 32 + c * 8;
            cpa16(base + OFF_AH + so, Ah + ga);
            cpa16(base + OFF_AL + so, Al + ga);
            size_t gb = bbase + (size_t)r * KPAD + kb * 32 + c * 8;
            cpa16(base + OFF_BH + so, Bh + gb);
            cpa16(base + OFF_BL + so, Bl + gb);
        }
        CPA_COMMIT();
    };

    issue(0, 0);

    for (int kb = 0; kb < NKB; kb++) {
        int st = kb & 1;
        if (kb + 1 < NKB) { issue(kb + 1, st ^ 1); CPA_WAIT(1); }
        else              { CPA_WAIT(0); }
        __syncthreads();

        uint32_t stbase = sb + st * STG_BYTES;
        #pragma unroll
        for (int c = 0; c < 2; c++) {
            uint32_t akoff = (uint32_t)(c * 16 + a_k8) * 2;
            uint32_t bkoff = (uint32_t)(c * 16 + b_k8) * 2;
            uint32_t ah[2][4], al[2][4];
            #pragma unroll
            for (int mt = 0; mt < 2; mt++) {
                uint32_t ra = stbase + (uint32_t)(wm + mt * 16 + a_row) * 80 + akoff;
                LDSM_X4(ah[mt], ra + OFF_AH);
                LDSM_X4(al[mt], ra + OFF_AL);
            }
            #pragma unroll
            for (int ntp = 0; ntp < 4; ntp++) {
                uint32_t rb = stbase + (uint32_t)(wn + ntp * 16 + b_row) * 80 + bkoff;
                uint32_t bh[4], bl[4];
                LDSM_X4(bh, rb + OFF_BH);
                LDSM_X4(bl, rb + OFF_BL);
                #pragma unroll
                for (int sub = 0; sub < 2; sub++) {
                    #pragma unroll
                    for (int mt = 0; mt < 2; mt++) {
                        float* d = acc[mt][ntp * 2 + sub];
                        MMA16816(d, ah[mt], bh[sub * 2], bh[sub * 2 + 1]);
                        MMA16816(d, ah[mt], bl[sub * 2], bl[sub * 2 + 1]);
                        MMA16816(d, al[mt], bh[sub * 2], bh[sub * 2 + 1]);
                    }
                }
            }
        }
        __syncthreads();
    }

    // --- epilogue ---
    const float* bias = ball + layer * NDIM;
    #pragma unroll
    for (int mt = 0; mt < 2; mt++) {
        #pragma unroll
        for (int hrow = 0; hrow < 2; hrow++) {
            int row = m0 + wm + mt * 16 + (lane >> 2) + hrow * 8;
            #pragma unroll
            for (int nt = 0; nt < 8; nt++) {
                int col = n0 + wn + nt * 8 + (lane & 3) * 2;
                if (col < NDIM) {
                    float v0 = acc[mt][nt][hrow * 2 + 0] + __ldg(bias + col);
                    float v1 = acc[mt][nt][hrow * 2 + 1] + __ldg(bias + col + 1);
                    if (FIRST) {
                        v0 = fmaxf(v0, 0.f); v1 = fmaxf(v1, 0.f);
                        uint32_t hi, lo;
                        split2(v0, v1, hi, lo);
                        *(uint32_t*)(g_hidh + (size_t)row * KP2 + col) = hi;
                        *(uint32_t*)(g_hidl + (size_t)row * KP2 + col) = lo;
                    } else {
                        float2 st; st.x = v0; st.y = v1;
                        *(float2*)(g_agg + (size_t)row * EMB + col) = st;
                    }
                }
            }
        }
    }
}

// ---------------------------------------------------------------------------
// BatchNorm stats (deterministic) + final-layer apply
// ---------------------------------------------------------------------------
__global__ void bn_part_kernel() {
    int c = threadIdx.x;
    if (c >= EMB) return;
    int r0   = blockIdx.x * 128;
    int rend = min(r0 + 128, N_NODES);
    float s = 0.f, q = 0.f;
    for (int r = r0; r < rend; r++) {
        float v = g_agg[r * EMB + c];
        s += v;
        q += v * v;
    }
    g_part[blockIdx.x * 2 * EMB + c]       = s;
    g_part[blockIdx.x * 2 * EMB + EMB + c] = q;
}
__global__ void bn_final_kernel(const float* __restrict__ gamma,
                                const float* __restrict__ beta, int layer) {
    int c = threadIdx.x;
    if (c >= EMB) return;
    float s = 0.f, q = 0.f;
    for (int b = 0; b < NCHUNK; b++) {
        s += g_part[b * 2 * EMB + c];
        q += g_part[b * 2 * EMB + EMB + c];
    }
    const float inv_n = 1.0f / (float)N_NODES;
    float mean = s * inv_n;
    float var  = q * inv_n - mean * mean;
    float sc = gamma[layer * EMB + c] * rsqrtf(var + 1e-5f);
    float sh = beta[layer * EMB + c] - mean * sc;
    g_stats[c]       = sc;
    g_stats[EMB + c] = sh;
}
__global__ void bn_apply_kernel(float* __restrict__ dst) {   // final layer, no relu
    int idx = blockIdx.x * blockDim.x + threadIdx.x;
    if (idx >= N_NODES * 75) return;
    int c = (idx % 75) * 4;
    float4 v = ((const float4*)g_agg)[idx];
    float4 r;
    r.x = v.x * g_stats[c + 0] + g_stats[EMB + c + 0];
    r.y = v.y * g_stats[c + 1] + g_stats[EMB + c + 1];
    r.z = v.z * g_stats[c + 2] + g_stats[EMB + c + 2];
    r.w = v.w * g_stats[c + 3] + g_stats[EMB + c + 3];
    ((float4*)dst)[idx] = r;
}

// ---------------------------------------------------------------------------
extern "C" void kernel_launch(void* const* d_in, const int* in_sizes, int n_in,
                              void* d_out, int out_size) {
    const int*   x     = (const int*)d_in[0];
    const int*   ei    = (const int*)d_in[1];
    const int*   ea    = (const int*)d_in[2];
    const float* xemb  = (const float*)d_in[3];
    const float* eemb  = (const float*)d_in[4];
    const float* W1    = (const float*)d_in[5];
    const float* b1    = (const float*)d_in[6];
    const float* W2    = (const float*)d_in[7];
    const float* b2    = (const float*)d_in[8];
    const float* gamma = (const float*)d_in[9];
    const float* beta  = (const float*)d_in[10];
    float* out = (float*)d_out;

    cudaFuncSetAttribute(mma_gemm_kernel<true>,
                         cudaFuncAttributeMaxDynamicSharedMemorySize, GEMM_SMEM);
    cudaFuncSetAttribute(mma_gemm_kernel<false>,
                         cudaFuncAttributeMaxDynamicSharedMemorySize, GEMM_SMEM);

    node_emb_kernel<<<(N_NODES * 75 + 255) / 256, 256>>>(x, xemb);
    prep_w1_kernel<<<(NLAYER * NP1 * KP1 + 255) / 256, 256>>>(W1);
    prep_w2_kernel<<<(NLAYER * NP2 * KP2 + 255) / 256, 256>>>(W2);

    reset_kernel<<<(N_NODES + 255) / 256, 256>>>();
    hist_kernel<<<(N_EDGES + 255) / 256, 256>>>(ei, ea);
    scan1_kernel<<<NBLK256, 256>>>();
    scan2_kernel<<<1, 256>>>();
    scan3_kernel<<<NBLK256, 256>>>();
    fill_kernel<<<(N_EDGES + 255) / 256, 256>>>(ei);
    sort_kernel<<<(N_NODES + 255) / 256, 256>>>();

    float* hsrc_first;
    cudaGetSymbolAddress((void**)&hsrc_first, g_h);
    float* hsrc_rest;
    cudaGetSymbolAddress((void**)&hsrc_rest, g_agg);

    for (int layer = 0; layer < NLAYER; layer++) {
        if (layer == 0)
            gather_kernel<false><<<(N_NODES * 32 + 255) / 256, 256>>>(hsrc_first, eemb, layer);
        else
            gather_kernel<true ><<<(N_NODES * 32 + 255) / 256, 256>>>(hsrc_rest, eemb, layer);
        mma_gemm_kernel<true ><<<dim3(M_PAD / 128, NP1 / 128), 256, GEMM_SMEM>>>(b1, layer);
        mma_gemm_kernel<false><<<dim3(M_PAD / 128, NP2 / 128), 256, GEMM_SMEM>>>(b2, layer);
        bn_part_kernel<<<NCHUNK, 320>>>();
        bn_final_kernel<<<1, 320>>>(gamma, beta, layer);
    }
    bn_apply_kernel<<<(N_NODES * 75 + 255) / 256, 256>>>(out);
}

// round 8
// speedup vs baseline: 3.5275x; 1.0313x over previous
#include <cuda_runtime.h>
#include <cuda_bf16.h>
#include <cstdint>

// ---------------------------------------------------------------------------
// GIN encoder, deterministic. GEMMs: mma.sync bf16 hi/lo (3-MMA), cp.async
// single-sync pipeline, ldmatrix loads. Gather: column-parallel, BN fused.
// ---------------------------------------------------------------------------
#define N_NODES 50000
#define M_PAD   50048           // 391 * 128
#define EMB     300
#define EMB2    600
#define N_EDGES 800000
#define NLAYER  5
#define NCHUNK  391
#define NBLK256 196             // ceil(50000/256)
#define GNODES  16              // nodes per gather block

// GEMM1: K=300 (pad 320), N=600 (pad 640). GEMM2: K=600 (pad 608), N=300 (pad 384).
#define KP1 320
#define NP1 640
#define KP2 608
#define NP2 384

// Scratch (device globals, zero-initialized; pad regions never written).
__device__ float g_h   [M_PAD * EMB];                        // layer-0 node emb
__device__ float g_agg [M_PAD * EMB];                        // GEMM2 out / BN in
__device__ __align__(16) __nv_bfloat16 g_aggh[M_PAD * KP1];
__device__ __align__(16) __nv_bfloat16 g_aggl[M_PAD * KP1];
__device__ __align__(16) __nv_bfloat16 g_hidh[M_PAD * KP2];
__device__ __align__(16) __nv_bfloat16 g_hidl[M_PAD * KP2];
__device__ float g_stats[2 * EMB];
__device__ float g_part [NCHUNK * 2 * EMB];
__device__ int   g_deg [N_NODES];
__device__ int   g_cur [N_NODES];
__device__ int   g_cnt [N_NODES * 9];
__device__ int   g_off [N_NODES + 1];
__device__ int   g_src [N_EDGES];
__device__ int   g_bsum[256];
// pre-transposed, padded, bf16-split weights: [layer][NPAD][KPAD]
__device__ __align__(16) __nv_bfloat16 g_w1h[NLAYER * NP1 * KP1];
__device__ __align__(16) __nv_bfloat16 g_w1l[NLAYER * NP1 * KP1];
__device__ __align__(16) __nv_bfloat16 g_w2h[NLAYER * NP2 * KP2];
__device__ __align__(16) __nv_bfloat16 g_w2l[NLAYER * NP2 * KP2];

#define MMA16816(d, a, b0, b1)                                                \
    asm volatile("mma.sync.aligned.m16n8k16.row.col.f32.bf16.bf16.f32 "       \
        "{%0,%1,%2,%3}, {%4,%5,%6,%7}, {%8,%9}, {%0,%1,%2,%3};"               \
        : "+f"((d)[0]), "+f"((d)[1]), "+f"((d)[2]), "+f"((d)[3])              \
        : "r"((a)[0]), "r"((a)[1]), "r"((a)[2]), "r"((a)[3]),                 \
          "r"(b0), "r"(b1))

#define LDSM_X4(r, addr)                                                      \
    asm volatile("ldmatrix.sync.aligned.m8n8.x4.shared.b16 {%0,%1,%2,%3}, [%4];" \
        : "=r"((r)[0]), "=r"((r)[1]), "=r"((r)[2]), "=r"((r)[3]) : "r"(addr))

__device__ __forceinline__ void cpa16(uint32_t dst, const void* src) {
    asm volatile("cp.async.cg.shared.global [%0], [%1], 16;" :: "r"(dst), "l"(src));
}
#define CPA_COMMIT() asm volatile("cp.async.commit_group;" ::: "memory")
#define CPA_WAIT(n)  asm volatile("cp.async.wait_group %0;" :: "n"(n) : "memory")

__device__ __forceinline__ uint32_t smem_u32(const void* p) {
    uint32_t a;
    asm("{ .reg .u64 t; cvta.to.shared.u64 t, %1; cvt.u32.u64 %0, t; }" : "=r"(a) : "l"(p));
    return a;
}
__device__ __forceinline__ uint32_t packbf(float lo, float hi) {
    uint32_t r;
    asm("cvt.rn.bf16x2.f32 %0, %1, %2;" : "=r"(r) : "f"(hi), "f"(lo));
    return r;
}
__device__ __forceinline__ void split2(float x, float y, uint32_t& hi, uint32_t& lo) {
    __nv_bfloat16 hx = __float2bfloat16(x), hy = __float2bfloat16(y);
    hi = ((uint32_t)__bfloat16_as_ushort(hy) << 16) | __bfloat16_as_ushort(hx);
    lo = packbf(x - __bfloat162float(hx), y - __bfloat162float(hy));
}

// ---------------------------------------------------------------------------
__global__ void node_emb_kernel(const int* __restrict__ x,
                                const float* __restrict__ xemb) {
    int idx = blockIdx.x * blockDim.x + threadIdx.x;
    if (idx >= N_NODES * 75) return;
    int row = idx / 75;
    int c4  = idx - row * 75;
    int a = x[2 * row];
    int b = x[2 * row + 1];
    float4 va = ((const float4*)(xemb + a * EMB))[c4];
    float4 vb = ((const float4*)(xemb + b * EMB))[c4];
    va.x += vb.x; va.y += vb.y; va.z += vb.z; va.w += vb.w;
    ((float4*)g_h)[idx] = va;
}

// ---------------------------------------------------------------------------
__global__ void prep_w1_kernel(const float* __restrict__ W1) {
    int idx = blockIdx.x * blockDim.x + threadIdx.x;
    if (idx >= NLAYER * NP1 * KP1) return;
    int layer = idx / (NP1 * KP1);
    int rem = idx - layer * NP1 * KP1;
    int n = rem / KP1, k = rem - n * KP1;
    float v = (n < EMB2 && k < EMB) ? W1[layer * EMB * EMB2 + k * EMB2 + n] : 0.f;
    __nv_bfloat16 h = __float2bfloat16(v);
    g_w1h[idx] = h;
    g_w1l[idx] = __float2bfloat16(v - __bfloat162float(h));
}
__global__ void prep_w2_kernel(const float* __restrict__ W2) {
    int idx = blockIdx.x * blockDim.x + threadIdx.x;
    if (idx >= NLAYER * NP2 * KP2) return;
    int layer = idx / (NP2 * KP2);
    int rem = idx - layer * NP2 * KP2;
    int n = rem / KP2, k = rem - n * KP2;
    float v = (n < EMB && k < EMB2) ? W2[layer * EMB2 * EMB + k * EMB + n] : 0.f;
    __nv_bfloat16 h = __float2bfloat16(v);
    g_w2h[idx] = h;
    g_w2l[idx] = __float2bfloat16(v - __bfloat162float(h));
}

// ---------------------------------------------------------------------------
// CSR build (deterministic)
// ---------------------------------------------------------------------------
__global__ void reset_kernel() {
    int i = blockIdx.x * blockDim.x + threadIdx.x;
    if (i < N_NODES) {
        g_deg[i] = 0; g_cur[i] = 0;
        #pragma unroll
        for (int c = 0; c < 9; c++) g_cnt[i * 9 + c] = 0;
    }
}
__global__ void hist_kernel(const int* __restrict__ ei,
                            const int* __restrict__ ea) {
    int e = blockIdx.x * blockDim.x + threadIdx.x;
    if (e >= N_EDGES) return;
    int dst = ei[N_EDGES + e];
    int c = ea[2 * e] * 3 + ea[2 * e + 1];
    atomicAdd(&g_deg[dst], 1);
    atomicAdd(&g_cnt[dst * 9 + c], 1);
}
__global__ void scan1_kernel() {
    __shared__ int s[256];
    int tid = threadIdx.x;
    int i = blockIdx.x * 256 + tid;
    s[tid] = (i < N_NODES) ? g_deg[i] : 0;
    __syncthreads();
    #pragma unroll
    for (int d = 1; d < 256; d <<= 1) {
        int t = (tid >= d) ? s[tid - d] : 0;
        __syncthreads();
        s[tid] += t;
        __syncthreads();
    }
    if (i < N_NODES) g_off[i + 1] = s[tid];
    if (tid == 255) g_bsum[blockIdx.x] = s[255];
}
__global__ void scan2_kernel() {
    __shared__ int s[256];
    int tid = threadIdx.x;
    s[tid] = (tid < NBLK256) ? g_bsum[tid] : 0;
    __syncthreads();
    #pragma unroll
    for (int d = 1; d < 256; d <<= 1) {
        int t = (tid >= d) ? s[tid - d] : 0;
        __syncthreads();
        s[tid] += t;
        __syncthreads();
    }
    g_bsum[tid] = s[tid];
}
__global__ void scan3_kernel() {
    int i = blockIdx.x * 256 + threadIdx.x;
    if (i < N_NODES && blockIdx.x > 0) g_off[i + 1] += g_bsum[blockIdx.x - 1];
    if (i == 0) g_off[0] = 0;
}
__global__ void fill_kernel(const int* __restrict__ ei) {
    int e = blockIdx.x * blockDim.x + threadIdx.x;
    if (e >= N_EDGES) return;
    int dst = ei[N_EDGES + e];
    int slot = atomicAdd(&g_cur[dst], 1);
    g_src[g_off[dst] + slot] = ei[e];
}
__global__ void sort_kernel() {          // sort src values; equal keys commute
    int n = blockIdx.x * blockDim.x + threadIdx.x;
    if (n >= N_NODES) return;
    int a = g_off[n], b = g_off[n + 1];
    for (int i = a + 1; i < b; i++) {
        int key = g_src[i];
        int j = i - 1;
        while (j >= a && g_src[j] > key) { g_src[j + 1] = g_src[j]; j--; }
        g_src[j + 1] = key;
    }
}

// ---------------------------------------------------------------------------
// Gather, column-parallel: 160 threads, thread t owns columns 2t,2t+1
// (t<150). GNODES nodes per block, sequential edge loop -> deterministic.
// agg[n] = f(src[n]) + selfc + sum_c cnt[n][c]*comb[c] + sum_e f(src[e]),
// f(v) = BN ? relu(v*sc+sh) : v. Output bf16 hi/lo at stride KP1.
// ---------------------------------------------------------------------------
template <bool BN>
__global__ void __launch_bounds__(160) gather_kernel(const float* __restrict__ srcdata,
                                                     const float* __restrict__ eemb,
                                                     int layer) {
    __shared__ __align__(16) float comb[9 * EMB];
    __shared__ __align__(16) float selfc[EMB];
    __shared__ __align__(16) float scs[EMB];
    __shared__ __align__(16) float shs[EMB];
    const float* emb = eemb + layer * 6 * EMB;
    for (int i = threadIdx.x; i < 9 * EMB; i += blockDim.x) {
        int c = i / EMB;
        int d = i - c * EMB;
        comb[i] = emb[(c / 3) * EMB + d] + emb[(c % 3) * EMB + d];
    }
    for (int i = threadIdx.x; i < EMB; i += blockDim.x) {
        selfc[i] = emb[4 * EMB + i] + emb[0 * EMB + i];
        if (BN) { scs[i] = g_stats[i]; shs[i] = g_stats[EMB + i]; }
    }
    __syncthreads();
    int t = threadIdx.x;
    if (t >= 150) return;
    int col = 2 * t;

    float2 scv, shv;
    if (BN) { scv = *(const float2*)&scs[col]; shv = *(const float2*)&shs[col]; }
    float2 sfc = *(const float2*)&selfc[col];

    int nodebase = blockIdx.x * GNODES;
    for (int g = 0; g < GNODES; g++) {
        int node = nodebase + g;
        if (node >= N_NODES) break;

        const float* base = srcdata + (size_t)node * EMB + col;
        float2 v = *(const float2*)base;
        if (BN) {
            v.x = fmaxf(fmaf(v.x, scv.x, shv.x), 0.f);
            v.y = fmaxf(fmaf(v.y, scv.y, shv.y), 0.f);
        }
        float2 acc;
        acc.x = v.x + sfc.x;
        acc.y = v.y + sfc.y;

        const int* cnt = g_cnt + node * 9;
        #pragma unroll
        for (int cb = 0; cb < 9; cb++) {
            int cc = cnt[cb];
            if (cc) {
                float cf = (float)cc;
                float2 b = *(const float2*)&comb[cb * EMB + col];
                acc.x = fmaf(cf, b.x, acc.x);
                acc.y = fmaf(cf, b.y, acc.y);
            }
        }

        int beg = g_off[node], end = g_off[node + 1];
        int idx = beg;
        for (; idx + 1 < end; idx += 2) {
            int s0 = g_src[idx], s1 = g_src[idx + 1];
            float2 a = *(const float2*)(srcdata + (size_t)s0 * EMB + col);
            float2 b = *(const float2*)(srcdata + (size_t)s1 * EMB + col);
            if (BN) {
                a.x = fmaxf(fmaf(a.x, scv.x, shv.x), 0.f);
                a.y = fmaxf(fmaf(a.y, scv.y, shv.y), 0.f);
                b.x = fmaxf(fmaf(b.x, scv.x, shv.x), 0.f);
                b.y = fmaxf(fmaf(b.y, scv.y, shv.y), 0.f);
            }
            acc.x += a.x + b.x;
            acc.y += a.y + b.y;
        }
        if (idx < end) {
            int s0 = g_src[idx];
            float2 a = *(const float2*)(srcdata + (size_t)s0 * EMB + col);
            if (BN) {
                a.x = fmaxf(fmaf(a.x, scv.x, shv.x), 0.f);
                a.y = fmaxf(fmaf(a.y, scv.y, shv.y), 0.f);
            }
            acc.x += a.x;
            acc.y += a.y;
        }

        uint32_t hi, lo;
        split2(acc.x, acc.y, hi, lo);
        *(uint32_t*)(g_aggh + (size_t)node * KP1 + col) = hi;
        *(uint32_t*)(g_aggl + (size_t)node * KP1 + col) = lo;
    }
}

// ---------------------------------------------------------------------------
// Pipelined bf16x3 GEMM: cp.async, ONE __syncthreads per K-chunk, ldmatrix.
// 128x128 CTA tile, BK=32, 8 warps (32x64 warp tile), 256 threads.
// ---------------------------------------------------------------------------
#define STG_BYTES 40960
#define OFF_AH 0
#define OFF_AL 10240
#define OFF_BH 20480
#define OFF_BL 30720
#define GEMM_SMEM (2 * STG_BYTES)

template <bool FIRST>
__global__ void __launch_bounds__(256, 2) mma_gemm_kernel(const float* __restrict__ ball,
                                                          int layer) {
    constexpr int NDIM = FIRST ? EMB2 : EMB;
    constexpr int KPAD = FIRST ? KP1 : KP2;
    constexpr int NPAD = FIRST ? NP1 : NP2;
    constexpr int NKB  = KPAD / 32;

    const __nv_bfloat16* __restrict__ Ah = FIRST ? g_aggh : g_hidh;
    const __nv_bfloat16* __restrict__ Al = FIRST ? g_aggl : g_hidl;
    const __nv_bfloat16* __restrict__ Bh = FIRST ? g_w1h : g_w2h;
    const __nv_bfloat16* __restrict__ Bl = FIRST ? g_w1l : g_w2l;

    extern __shared__ __align__(16) char sm[];
    uint32_t sb = smem_u32(sm);

    int tid  = threadIdx.x;
    int lane = tid & 31;
    int wid  = tid >> 5;
    int wm   = (wid & 3) * 32;
    int wn   = (wid >> 2) * 64;
    int m0   = blockIdx.x * 128;
    int n0   = blockIdx.y * 128;

    int lg = lane >> 3, lj = lane & 7;
    int a_row = (lg & 1) * 8 + lj;
    int a_k8  = (lg >> 1) * 8;
    int b_row = (lg >> 1) * 8 + lj;
    int b_k8  = (lg & 1) * 8;

    float acc[2][8][4];
    #pragma unroll
    for (int mt = 0; mt < 2; mt++)
        #pragma unroll
        for (int nt = 0; nt < 8; nt++)
            #pragma unroll
            for (int q = 0; q < 4; q++) acc[mt][nt][q] = 0.f;

    const size_t bbase = ((size_t)layer * NPAD + n0) * KPAD;

    auto issue = [&](int kb, int st) {
        uint32_t base = sb + st * STG_BYTES;
        #pragma unroll
        for (int i = 0; i < 2; i++) {
            int v = tid + i * 256;
            int r = v >> 2;
            int c = v & 3;
            uint32_t so = r * 80 + c * 16;
            size_t ga = (size_t)(m0 + r) * KPAD + kb * 32 + c * 8;
            cpa16(base + OFF_AH + so, Ah + ga);
            cpa16(base + OFF_AL + so, Al + ga);
            size_t gb = bbase + (size_t)r * KPAD + kb * 32 + c * 8;
            cpa16(base + OFF_BH + so, Bh + gb);
            cpa16(base + OFF_BL + so, Bl + gb);
        }
        CPA_COMMIT();
    };

    issue(0, 0);

    for (int kb = 0; kb < NKB; kb++) {
        int st = kb & 1;
        CPA_WAIT(0);            // stage st data landed
        __syncthreads();        // + every warp finished consuming stage st^1
        if (kb + 1 < NKB) issue(kb + 1, st ^ 1);   // refill st^1 (safe: barrier passed)

        uint32_t stbase = sb + st * STG_BYTES;
        #pragma unroll
        for (int c = 0; c < 2; c++) {
            uint32_t akoff = (uint32_t)(c * 16 + a_k8) * 2;
            uint32_t bkoff = (uint32_t)(c * 16 + b_k8) * 2;
            uint32_t ah[2][4], al[2][4];
            #pragma unroll
            for (int mt = 0; mt < 2; mt++) {
                uint32_t ra = stbase + (uint32_t)(wm + mt * 16 + a_row) * 80 + akoff;
                LDSM_X4(ah[mt], ra + OFF_AH);
                LDSM_X4(al[mt], ra + OFF_AL);
            }
            #pragma unroll
            for (int ntp = 0; ntp < 4; ntp++) {
                uint32_t rb = stbase + (uint32_t)(wn + ntp * 16 + b_row) * 80 + bkoff;
                uint32_t bh[4], bl[4];
                LDSM_X4(bh, rb + OFF_BH);
                LDSM_X4(bl, rb + OFF_BL);
                #pragma unroll
                for (int sub = 0; sub < 2; sub++) {
                    #pragma unroll
                    for (int mt = 0; mt < 2; mt++) {
                        float* d = acc[mt][ntp * 2 + sub];
                        MMA16816(d, ah[mt], bh[sub * 2], bh[sub * 2 + 1]);
                        MMA16816(d, ah[mt], bl[sub * 2], bl[sub * 2 + 1]);
                        MMA16816(d, al[mt], bh[sub * 2], bh[sub * 2 + 1]);
                    }
                }
            }
        }
    }

    // --- epilogue ---
    const float* bias = ball + layer * NDIM;
    #pragma unroll
    for (int mt = 0; mt < 2; mt++) {
        #pragma unroll
        for (int hrow = 0; hrow < 2; hrow++) {
            int row = m0 + wm + mt * 16 + (lane >> 2) + hrow * 8;
            #pragma unroll
            for (int nt = 0; nt < 8; nt++) {
                int col = n0 + wn + nt * 8 + (lane & 3) * 2;
                if (col < NDIM) {
                    float v0 = acc[mt][nt][hrow * 2 + 0] + __ldg(bias + col);
                    float v1 = acc[mt][nt][hrow * 2 + 1] + __ldg(bias + col + 1);
                    if (FIRST) {
                        v0 = fmaxf(v0, 0.f); v1 = fmaxf(v1, 0.f);
                        uint32_t hi, lo;
                        split2(v0, v1, hi, lo);
                        *(uint32_t*)(g_hidh + (size_t)row * KP2 + col) = hi;
                        *(uint32_t*)(g_hidl + (size_t)row * KP2 + col) = lo;
                    } else {
                        float2 st; st.x = v0; st.y = v1;
                        *(float2*)(g_agg + (size_t)row * EMB + col) = st;
                    }
                }
            }
        }
    }
}

// ---------------------------------------------------------------------------
// BatchNorm stats (deterministic) + final-layer apply
// ---------------------------------------------------------------------------
__global__ void bn_part_kernel() {
    int c = threadIdx.x;
    if (c >= EMB) return;
    int r0   = blockIdx.x * 128;
    int rend = min(r0 + 128, N_NODES);
    float s = 0.f, q = 0.f;
    for (int r = r0; r < rend; r++) {
        float v = g_agg[r * EMB + c];
        s += v;
        q += v * v;
    }
    g_part[blockIdx.x * 2 * EMB + c]       = s;
    g_part[blockIdx.x * 2 * EMB + EMB + c] = q;
}
__global__ void bn_final_kernel(const float* __restrict__ gamma,
                                const float* __restrict__ beta, int layer) {
    int c = threadIdx.x;
    if (c >= EMB) return;
    float s = 0.f, q = 0.f;
    for (int b = 0; b < NCHUNK; b++) {
        s += g_part[b * 2 * EMB + c];
        q += g_part[b * 2 * EMB + EMB + c];
    }
    const float inv_n = 1.0f / (float)N_NODES;
    float mean = s * inv_n;
    float var  = q * inv_n - mean * mean;
    float sc = gamma[layer * EMB + c] * rsqrtf(var + 1e-5f);
    float sh = beta[layer * EMB + c] - mean * sc;
    g_stats[c]       = sc;
    g_stats[EMB + c] = sh;
}
__global__ void bn_apply_kernel(float* __restrict__ dst) {   // final layer, no relu
    int idx = blockIdx.x * blockDim.x + threadIdx.x;
    if (idx >= N_NODES * 75) return;
    int c = (idx % 75) * 4;
    float4 v = ((const float4*)g_agg)[idx];
    float4 r;
    r.x = v.x * g_stats[c + 0] + g_stats[EMB + c + 0];
    r.y = v.y * g_stats[c + 1] + g_stats[EMB + c + 1];
    r.z = v.z * g_stats[c + 2] + g_stats[EMB + c + 2];
    r.w = v.w * g_stats[c + 3] + g_stats[EMB + c + 3];
    ((float4*)dst)[idx] = r;
}

// ---------------------------------------------------------------------------
extern "C" void kernel_launch(void* const* d_in, const int* in_sizes, int n_in,
                              void* d_out, int out_size) {
    const int*   x     = (const int*)d_in[0];
    const int*   ei    = (const int*)d_in[1];
    const int*   ea    = (const int*)d_in[2];
    const float* xemb  = (const float*)d_in[3];
    const float* eemb  = (const float*)d_in[4];
    const float* W1    = (const float*)d_in[5];
    const float* b1    = (const float*)d_in[6];
    const float* W2    = (const float*)d_in[7];
    const float* b2    = (const float*)d_in[8];
    const float* gamma = (const float*)d_in[9];
    const float* beta  = (const float*)d_in[10];
    float* out = (float*)d_out;

    cudaFuncSetAttribute(mma_gemm_kernel<true>,
                         cudaFuncAttributeMaxDynamicSharedMemorySize, GEMM_SMEM);
    cudaFuncSetAttribute(mma_gemm_kernel<false>,
                         cudaFuncAttributeMaxDynamicSharedMemorySize, GEMM_SMEM);

    node_emb_kernel<<<(N_NODES * 75 + 255) / 256, 256>>>(x, xemb);
    prep_w1_kernel<<<(NLAYER * NP1 * KP1 + 255) / 256, 256>>>(W1);
    prep_w2_kernel<<<(NLAYER * NP2 * KP2 + 255) / 256, 256>>>(W2);

    reset_kernel<<<(N_NODES + 255) / 256, 256>>>();
    hist_kernel<<<(N_EDGES + 255) / 256, 256>>>(ei, ea);
    scan1_kernel<<<NBLK256, 256>>>();
    scan2_kernel<<<1, 256>>>();
    scan3_kernel<<<NBLK256, 256>>>();
    fill_kernel<<<(N_EDGES + 255) / 256, 256>>>(ei);
    sort_kernel<<<(N_NODES + 255) / 256, 256>>>();

    float* hsrc_first;
    cudaGetSymbolAddress((void**)&hsrc_first, g_h);
    float* hsrc_rest;
    cudaGetSymbolAddress((void**)&hsrc_rest, g_agg);

    const int ggrid = (N_NODES + GNODES - 1) / GNODES;
    for (int layer = 0; layer < NLAYER; layer++) {
        if (layer == 0)
            gather_kernel<false><<<ggrid, 160>>>(hsrc_first, eemb, layer);
        else
            gather_kernel<true ><<<ggrid, 160>>>(hsrc_rest, eemb, layer);
        mma_gemm_kernel<true ><<<dim3(M_PAD / 128, NP1 / 128), 256, GEMM_SMEM>>>(b1, layer);
        mma_gemm_kernel<false><<<dim3(M_PAD / 128, NP2 / 128), 256, GEMM_SMEM>>>(b2, layer);
        bn_part_kernel<<<NCHUNK, 320>>>();
        bn_final_kernel<<<1, 320>>>(gamma, beta, layer);
    }
    bn_apply_kernel<<<(N_NODES * 75 + 255) / 256, 256>>>(out);
}

// round 9
// speedup vs baseline: 3.6715x; 1.0408x over previous
#include <cuda_runtime.h>
#include <cuda_bf16.h>
#include <cstdint>

// ---------------------------------------------------------------------------
// GIN encoder, deterministic. GEMM1: 128x128 tile; GEMM2: 256x64 tile with
// fused BN partial stats. mma.sync bf16 hi/lo (3-MMA), cp.async, ldmatrix.
// ---------------------------------------------------------------------------
#define N_NODES 50000
#define M_PAD   50176           // 392*128 = 196*256
#define EMB     300
#define EMB2    600
#define N_EDGES 800000
#define NLAYER  5
#define NCHUNK  196             // BN row chunks of 256 (= GEMM2 M-tiles)
#define NBLK256 196             // ceil(50000/256) for scan
#define GNODES  16

#define KP1 320
#define NP1 640
#define KP2 608
#define NP2 320

// Scratch (device globals, zero-initialized; pad regions never written).
__device__ float g_h   [M_PAD * EMB];
__device__ float g_agg [M_PAD * EMB];
__device__ __align__(16) __nv_bfloat16 g_aggh[M_PAD * KP1];
__device__ __align__(16) __nv_bfloat16 g_aggl[M_PAD * KP1];
__device__ __align__(16) __nv_bfloat16 g_hidh[M_PAD * KP2];
__device__ __align__(16) __nv_bfloat16 g_hidl[M_PAD * KP2];
__device__ float g_stats[2 * EMB];
__device__ float g_part [NCHUNK * 2 * EMB];
__device__ int   g_deg [N_NODES];
__device__ int   g_cur [N_NODES];
__device__ int   g_cnt [N_NODES * 9];
__device__ int   g_off [N_NODES + 1];
__device__ int   g_src [N_EDGES];
__device__ int   g_bsum[256];
__device__ __align__(16) __nv_bfloat16 g_w1h[NLAYER * NP1 * KP1];
__device__ __align__(16) __nv_bfloat16 g_w1l[NLAYER * NP1 * KP1];
__device__ __align__(16) __nv_bfloat16 g_w2h[NLAYER * NP2 * KP2];
__device__ __align__(16) __nv_bfloat16 g_w2l[NLAYER * NP2 * KP2];

#define MMA16816(d, a, b0, b1)                                                \
    asm volatile("mma.sync.aligned.m16n8k16.row.col.f32.bf16.bf16.f32 "       \
        "{%0,%1,%2,%3}, {%4,%5,%6,%7}, {%8,%9}, {%0,%1,%2,%3};"               \
        : "+f"((d)[0]), "+f"((d)[1]), "+f"((d)[2]), "+f"((d)[3])              \
        : "r"((a)[0]), "r"((a)[1]), "r"((a)[2]), "r"((a)[3]),                 \
          "r"(b0), "r"(b1))

#define LDSM_X4(r, addr)                                                      \
    asm volatile("ldmatrix.sync.aligned.m8n8.x4.shared.b16 {%0,%1,%2,%3}, [%4];" \
        : "=r"((r)[0]), "=r"((r)[1]), "=r"((r)[2]), "=r"((r)[3]) : "r"(addr))

__device__ __forceinline__ void cpa16(uint32_t dst, const void* src) {
    asm volatile("cp.async.cg.shared.global [%0], [%1], 16;" :: "r"(dst), "l"(src));
}
#define CPA_COMMIT() asm volatile("cp.async.commit_group;" ::: "memory")
#define CPA_WAIT(n)  asm volatile("cp.async.wait_group %0;" :: "n"(n) : "memory")

__device__ __forceinline__ uint32_t smem_u32(const void* p) {
    uint32_t a;
    asm("{ .reg .u64 t; cvta.to.shared.u64 t, %1; cvt.u32.u64 %0, t; }" : "=r"(a) : "l"(p));
    return a;
}
__device__ __forceinline__ uint32_t packbf(float lo, float hi) {
    uint32_t r;
    asm("cvt.rn.bf16x2.f32 %0, %1, %2;" : "=r"(r) : "f"(hi), "f"(lo));
    return r;
}
__device__ __forceinline__ void split2(float x, float y, uint32_t& hi, uint32_t& lo) {
    __nv_bfloat16 hx = __float2bfloat16(x), hy = __float2bfloat16(y);
    hi = ((uint32_t)__bfloat16_as_ushort(hy) << 16) | __bfloat16_as_ushort(hx);
    lo = packbf(x - __bfloat162float(hx), y - __bfloat162float(hy));
}

// ---------------------------------------------------------------------------
__global__ void node_emb_kernel(const int* __restrict__ x,
                                const float* __restrict__ xemb) {
    int idx = blockIdx.x * blockDim.x + threadIdx.x;
    if (idx >= N_NODES * 75) return;
    int row = idx / 75;
    int c4  = idx - row * 75;
    int a = x[2 * row];
    int b = x[2 * row + 1];
    float4 va = ((const float4*)(xemb + a * EMB))[c4];
    float4 vb = ((const float4*)(xemb + b * EMB))[c4];
    va.x += vb.x; va.y += vb.y; va.z += vb.z; va.w += vb.w;
    ((float4*)g_h)[idx] = va;
}

// ---------------------------------------------------------------------------
__global__ void prep_w1_kernel(const float* __restrict__ W1) {
    int idx = blockIdx.x * blockDim.x + threadIdx.x;
    if (idx >= NLAYER * NP1 * KP1) return;
    int layer = idx / (NP1 * KP1);
    int rem = idx - layer * NP1 * KP1;
    int n = rem / KP1, k = rem - n * KP1;
    float v = (n < EMB2 && k < EMB) ? W1[layer * EMB * EMB2 + k * EMB2 + n] : 0.f;
    __nv_bfloat16 h = __float2bfloat16(v);
    g_w1h[idx] = h;
    g_w1l[idx] = __float2bfloat16(v - __bfloat162float(h));
}
__global__ void prep_w2_kernel(const float* __restrict__ W2) {
    int idx = blockIdx.x * blockDim.x + threadIdx.x;
    if (idx >= NLAYER * NP2 * KP2) return;
    int layer = idx / (NP2 * KP2);
    int rem = idx - layer * NP2 * KP2;
    int n = rem / KP2, k = rem - n * KP2;
    float v = (n < EMB && k < EMB2) ? W2[layer * EMB2 * EMB + k * EMB + n] : 0.f;
    __nv_bfloat16 h = __float2bfloat16(v);
    g_w2h[idx] = h;
    g_w2l[idx] = __float2bfloat16(v - __bfloat162float(h));
}

// ---------------------------------------------------------------------------
// CSR build (deterministic)
// ---------------------------------------------------------------------------
__global__ void reset_kernel() {
    int i = blockIdx.x * blockDim.x + threadIdx.x;
    if (i < N_NODES) {
        g_deg[i] = 0; g_cur[i] = 0;
        #pragma unroll
        for (int c = 0; c < 9; c++) g_cnt[i * 9 + c] = 0;
    }
}
__global__ void hist_kernel(const int* __restrict__ ei,
                            const int* __restrict__ ea) {
    int e = blockIdx.x * blockDim.x + threadIdx.x;
    if (e >= N_EDGES) return;
    int dst = ei[N_EDGES + e];
    int c = ea[2 * e] * 3 + ea[2 * e + 1];
    atomicAdd(&g_deg[dst], 1);
    atomicAdd(&g_cnt[dst * 9 + c], 1);
}
__global__ void scan1_kernel() {
    __shared__ int s[256];
    int tid = threadIdx.x;
    int i = blockIdx.x * 256 + tid;
    s[tid] = (i < N_NODES) ? g_deg[i] : 0;
    __syncthreads();
    #pragma unroll
    for (int d = 1; d < 256; d <<= 1) {
        int t = (tid >= d) ? s[tid - d] : 0;
        __syncthreads();
        s[tid] += t;
        __syncthreads();
    }
    if (i < N_NODES) g_off[i + 1] = s[tid];
    if (tid == 255) g_bsum[blockIdx.x] = s[255];
}
__global__ void scan2_kernel() {
    __shared__ int s[256];
    int tid = threadIdx.x;
    s[tid] = (tid < NBLK256) ? g_bsum[tid] : 0;
    __syncthreads();
    #pragma unroll
    for (int d = 1; d < 256; d <<= 1) {
        int t = (tid >= d) ? s[tid - d] : 0;
        __syncthreads();
        s[tid] += t;
        __syncthreads();
    }
    g_bsum[tid] = s[tid];
}
__global__ void scan3_kernel() {
    int i = blockIdx.x * 256 + threadIdx.x;
    if (i < N_NODES && blockIdx.x > 0) g_off[i + 1] += g_bsum[blockIdx.x - 1];
    if (i == 0) g_off[0] = 0;
}
__global__ void fill_kernel(const int* __restrict__ ei) {
    int e = blockIdx.x * blockDim.x + threadIdx.x;
    if (e >= N_EDGES) return;
    int dst = ei[N_EDGES + e];
    int slot = atomicAdd(&g_cur[dst], 1);
    g_src[g_off[dst] + slot] = ei[e];
}
__global__ void sort_kernel() {
    int n = blockIdx.x * blockDim.x + threadIdx.x;
    if (n >= N_NODES) return;
    int a = g_off[n], b = g_off[n + 1];
    for (int i = a + 1; i < b; i++) {
        int key = g_src[i];
        int j = i - 1;
        while (j >= a && g_src[j] > key) { g_src[j + 1] = g_src[j]; j--; }
        g_src[j + 1] = key;
    }
}

// ---------------------------------------------------------------------------
// Gather, column-parallel (BN fused when BN=true). Deterministic.
// ---------------------------------------------------------------------------
template <bool BN>
__global__ void __launch_bounds__(160) gather_kernel(const float* __restrict__ srcdata,
                                                     const float* __restrict__ eemb,
                                                     int layer) {
    __shared__ __align__(16) float comb[9 * EMB];
    __shared__ __align__(16) float selfc[EMB];
    __shared__ __align__(16) float scs[EMB];
    __shared__ __align__(16) float shs[EMB];
    const float* emb = eemb + layer * 6 * EMB;
    for (int i = threadIdx.x; i < 9 * EMB; i += blockDim.x) {
        int c = i / EMB;
        int d = i - c * EMB;
        comb[i] = emb[(c / 3) * EMB + d] + emb[(c % 3) * EMB + d];
    }
    for (int i = threadIdx.x; i < EMB; i += blockDim.x) {
        selfc[i] = emb[4 * EMB + i] + emb[0 * EMB + i];
        if (BN) { scs[i] = g_stats[i]; shs[i] = g_stats[EMB + i]; }
    }
    __syncthreads();
    int t = threadIdx.x;
    if (t >= 150) return;
    int col = 2 * t;

    float2 scv, shv;
    if (BN) { scv = *(const float2*)&scs[col]; shv = *(const float2*)&shs[col]; }
    float2 sfc = *(const float2*)&selfc[col];

    int nodebase = blockIdx.x * GNODES;
    for (int g = 0; g < GNODES; g++) {
        int node = nodebase + g;
        if (node >= N_NODES) break;

        float2 v = *(const float2*)(srcdata + (size_t)node * EMB + col);
        if (BN) {
            v.x = fmaxf(fmaf(v.x, scv.x, shv.x), 0.f);
            v.y = fmaxf(fmaf(v.y, scv.y, shv.y), 0.f);
        }
        float2 acc;
        acc.x = v.x + sfc.x;
        acc.y = v.y + sfc.y;

        const int* cnt = g_cnt + node * 9;
        #pragma unroll
        for (int cb = 0; cb < 9; cb++) {
            int cc = cnt[cb];
            if (cc) {
                float cf = (float)cc;
                float2 b = *(const float2*)&comb[cb * EMB + col];
                acc.x = fmaf(cf, b.x, acc.x);
                acc.y = fmaf(cf, b.y, acc.y);
            }
        }

        int beg = g_off[node], end = g_off[node + 1];
        int idx = beg;
        for (; idx + 1 < end; idx += 2) {
            int s0 = g_src[idx], s1 = g_src[idx + 1];
            float2 a = *(const float2*)(srcdata + (size_t)s0 * EMB + col);
            float2 b = *(const float2*)(srcdata + (size_t)s1 * EMB + col);
            if (BN) {
                a.x = fmaxf(fmaf(a.x, scv.x, shv.x), 0.f);
                a.y = fmaxf(fmaf(a.y, scv.y, shv.y), 0.f);
                b.x = fmaxf(fmaf(b.x, scv.x, shv.x), 0.f);
                b.y = fmaxf(fmaf(b.y, scv.y, shv.y), 0.f);
            }
            acc.x += a.x + b.x;
            acc.y += a.y + b.y;
        }
        if (idx < end) {
            int s0 = g_src[idx];
            float2 a = *(const float2*)(srcdata + (size_t)s0 * EMB + col);
            if (BN) {
                a.x = fmaxf(fmaf(a.x, scv.x, shv.x), 0.f);
                a.y = fmaxf(fmaf(a.y, scv.y, shv.y), 0.f);
            }
            acc.x += a.x;
            acc.y += a.y;
        }

        uint32_t hi, lo;
        split2(acc.x, acc.y, hi, lo);
        *(uint32_t*)(g_aggh + (size_t)node * KP1 + col) = hi;
        *(uint32_t*)(g_aggl + (size_t)node * KP1 + col) = lo;
    }
}

// ---------------------------------------------------------------------------
// GEMM1: 128x128 tile, 8 warps (4Mx2N, warp 32x64), relu, bf16 hi/lo out.
// ---------------------------------------------------------------------------
#define STG_BYTES 40960
#define OFF_AH 0
#define OFF_AL 10240
#define OFF_BH 20480
#define OFF_BL 30720
#define GEMM1_SMEM (2 * STG_BYTES)

__global__ void __launch_bounds__(256, 2) gemm1_kernel(const float* __restrict__ ball,
                                                       int layer) {
    constexpr int NDIM = EMB2, KPAD = KP1, NPAD = NP1, NKB = KP1 / 32;

    extern __shared__ __align__(16) char sm[];
    uint32_t sb = smem_u32(sm);

    int tid  = threadIdx.x;
    int lane = tid & 31;
    int wid  = tid >> 5;
    int wm   = (wid & 3) * 32;
    int wn   = (wid >> 2) * 64;
    int m0   = blockIdx.x * 128;
    int n0   = blockIdx.y * 128;

    int lg = lane >> 3, lj = lane & 7;
    int a_row = (lg & 1) * 8 + lj;
    int a_k8  = (lg >> 1) * 8;
    int b_row = (lg >> 1) * 8 + lj;
    int b_k8  = (lg & 1) * 8;

    float acc[2][8][4];
    #pragma unroll
    for (int mt = 0; mt < 2; mt++)
        #pragma unroll
        for (int nt = 0; nt < 8; nt++)
            #pragma unroll
            for (int q = 0; q < 4; q++) acc[mt][nt][q] = 0.f;

    const size_t bbase = ((size_t)layer * NPAD + n0) * KPAD;

    auto issue = [&](int kb, int st) {
        uint32_t base = sb + st * STG_BYTES;
        #pragma unroll
        for (int i = 0; i < 2; i++) {
            int v = tid + i * 256;
            int r = v >> 2;
            int c = v & 3;
            uint32_t so = r * 80 + c * 16;
            size_t ga = (size_t)(m0 + r) * KPAD + kb * 32 + c * 8;
            cpa16(base + OFF_AH + so, g_aggh + ga);
            cpa16(base + OFF_AL + so, g_aggl + ga);
            size_t gb = bbase + (size_t)r * KPAD + kb * 32 + c * 8;
            cpa16(base + OFF_BH + so, g_w1h + gb);
            cpa16(base + OFF_BL + so, g_w1l + gb);
        }
        CPA_COMMIT();
    };

    issue(0, 0);

    for (int kb = 0; kb < NKB; kb++) {
        int st = kb & 1;
        CPA_WAIT(0);
        __syncthreads();
        if (kb + 1 < NKB) issue(kb + 1, st ^ 1);

        uint32_t stbase = sb + st * STG_BYTES;
        #pragma unroll
        for (int c = 0; c < 2; c++) {
            uint32_t akoff = (uint32_t)(c * 16 + a_k8) * 2;
            uint32_t bkoff = (uint32_t)(c * 16 + b_k8) * 2;
            uint32_t ah[2][4], al[2][4];
            #pragma unroll
            for (int mt = 0; mt < 2; mt++) {
                uint32_t ra = stbase + (uint32_t)(wm + mt * 16 + a_row) * 80 + akoff;
                LDSM_X4(ah[mt], ra + OFF_AH);
                LDSM_X4(al[mt], ra + OFF_AL);
            }
            #pragma unroll
            for (int ntp = 0; ntp < 4; ntp++) {
                uint32_t rb = stbase + (uint32_t)(wn + ntp * 16 + b_row) * 80 + bkoff;
                uint32_t bh[4], bl[4];
                LDSM_X4(bh, rb + OFF_BH);
                LDSM_X4(bl, rb + OFF_BL);
                #pragma unroll
                for (int sub = 0; sub < 2; sub++) {
                    #pragma unroll
                    for (int mt = 0; mt < 2; mt++) {
                        float* d = acc[mt][ntp * 2 + sub];
                        MMA16816(d, ah[mt], bh[sub * 2], bh[sub * 2 + 1]);
                        MMA16816(d, ah[mt], bl[sub * 2], bl[sub * 2 + 1]);
                        MMA16816(d, al[mt], bh[sub * 2], bh[sub * 2 + 1]);
                    }
                }
            }
        }
    }

    const float* bias = ball + layer * NDIM;
    #pragma unroll
    for (int mt = 0; mt < 2; mt++) {
        #pragma unroll
        for (int hrow = 0; hrow < 2; hrow++) {
            int row = m0 + wm + mt * 16 + (lane >> 2) + hrow * 8;
            #pragma unroll
            for (int nt = 0; nt < 8; nt++) {
                int col = n0 + wn + nt * 8 + (lane & 3) * 2;
                if (col < NDIM) {
                    float v0 = fmaxf(acc[mt][nt][hrow * 2 + 0] + __ldg(bias + col), 0.f);
                    float v1 = fmaxf(acc[mt][nt][hrow * 2 + 1] + __ldg(bias + col + 1), 0.f);
                    uint32_t hi, lo;
                    split2(v0, v1, hi, lo);
                    *(uint32_t*)(g_hidh + (size_t)row * KP2 + col) = hi;
                    *(uint32_t*)(g_hidl + (size_t)row * KP2 + col) = lo;
                }
            }
        }
    }
}

// ---------------------------------------------------------------------------
// GEMM2: 256x64 tile, 8 M-warps (warp 32x64), fp32 out + fused BN partials.
// smem per stage: A 256x40x2 arrays (40960) + B 64x40x2 (10240) = 51200.
// ---------------------------------------------------------------------------
#define STG2_BYTES 51200
#define OFF2_AH 0
#define OFF2_AL 20480
#define OFF2_BH 40960
#define OFF2_BL 46080
#define GEMM2_SMEM (2 * STG2_BYTES)

__global__ void __launch_bounds__(256, 2) gemm2_kernel(const float* __restrict__ ball,
                                                       int layer) {
    constexpr int NDIM = EMB, KPAD = KP2, NPAD = NP2, NKB = KP2 / 32;

    extern __shared__ __align__(16) char sm[];
    uint32_t sb = smem_u32(sm);

    int tid  = threadIdx.x;
    int lane = tid & 31;
    int wid  = tid >> 5;
    int wm   = wid * 32;                 // 8 M-warps
    int m0   = blockIdx.x * 256;
    int n0   = blockIdx.y * 64;

    int lg = lane >> 3, lj = lane & 7;
    int a_row = (lg & 1) * 8 + lj;
    int a_k8  = (lg >> 1) * 8;
    int b_row = (lg >> 1) * 8 + lj;
    int b_k8  = (lg & 1) * 8;

    float acc[2][8][4];
    #pragma unroll
    for (int mt = 0; mt < 2; mt++)
        #pragma unroll
        for (int nt = 0; nt < 8; nt++)
            #pragma unroll
            for (int q = 0; q < 4; q++) acc[mt][nt][q] = 0.f;

    const size_t bbase = ((size_t)layer * NPAD + n0) * KPAD;

    // per stage: A hi/lo 256 rows, B hi/lo 64 rows; 2560 cp.async over 256 thr
    auto issue = [&](int kb, int st) {
        uint32_t base = sb + st * STG2_BYTES;
        #pragma unroll
        for (int i = 0; i < 10; i++) {
            int v = tid + i * 256;
            if (v < 2048) {                       // A (hi then lo)
                int arr = v >> 10;
                int rem = v & 1023;
                int r = rem >> 2, c = rem & 3;
                uint32_t so = (arr ? OFF2_AL : OFF2_AH) + r * 80 + c * 16;
                size_t ga = (size_t)(m0 + r) * KPAD + kb * 32 + c * 8;
                cpa16(base + so, (arr ? g_hidl : g_hidh) + ga);
            } else {                              // B (hi then lo)
                int v2 = v - 2048;
                int arr = v2 >> 8;
                int rem = v2 & 255;
                int r = rem >> 2, c = rem & 3;
                uint32_t so = (arr ? OFF2_BL : OFF2_BH) + r * 80 + c * 16;
                size_t gb = bbase + (size_t)r * KPAD + kb * 32 + c * 8;
                cpa16(base + so, (arr ? g_w2l : g_w2h) + gb);
            }
        }
        CPA_COMMIT();
    };

    issue(0, 0);

    for (int kb = 0; kb < NKB; kb++) {
        int st = kb & 1;
        CPA_WAIT(0);
        __syncthreads();
        if (kb + 1 < NKB) issue(kb + 1, st ^ 1);

        uint32_t stbase = sb + st * STG2_BYTES;
        #pragma unroll
        for (int c = 0; c < 2; c++) {
            uint32_t akoff = (uint32_t)(c * 16 + a_k8) * 2;
            uint32_t bkoff = (uint32_t)(c * 16 + b_k8) * 2;
            uint32_t ah[2][4], al[2][4];
            #pragma unroll
            for (int mt = 0; mt < 2; mt++) {
                uint32_t ra = stbase + (uint32_t)(wm + mt * 16 + a_row) * 80 + akoff;
                LDSM_X4(ah[mt], ra + OFF2_AH);
                LDSM_X4(al[mt], ra + OFF2_AL);
            }
            #pragma unroll
            for (int ntp = 0; ntp < 4; ntp++) {
                uint32_t rb = stbase + (uint32_t)(ntp * 16 + b_row) * 80 + bkoff;
                uint32_t bh[4], bl[4];
                LDSM_X4(bh, rb + OFF2_BH);
                LDSM_X4(bl, rb + OFF2_BL);
                #pragma unroll
                for (int sub = 0; sub < 2; sub++) {
                    #pragma unroll
                    for (int mt = 0; mt < 2; mt++) {
                        float* d = acc[mt][ntp * 2 + sub];
                        MMA16816(d, ah[mt], bh[sub * 2], bh[sub * 2 + 1]);
                        MMA16816(d, ah[mt], bl[sub * 2], bl[sub * 2 + 1]);
                        MMA16816(d, al[mt], bh[sub * 2], bh[sub * 2 + 1]);
                    }
                }
            }
        }
    }

    // --- epilogue: store fp32 + fused BN partial sums (rows < N_NODES) ---
    __syncthreads();                        // smem now reusable for reduction
    float* red = (float*)sm;                // [8 warps][8 nt][4 L][4 vals]
    const float* bias = ball + layer * NDIM;

    #pragma unroll
    for (int nt = 0; nt < 8; nt++) {
        int col = n0 + nt * 8 + (lane & 3) * 2;
        float bv0 = (col     < NDIM) ? __ldg(bias + col)     : 0.f;
        float bv1 = (col + 1 < NDIM) ? __ldg(bias + col + 1) : 0.f;
        float s0 = 0.f, q0 = 0.f, s1 = 0.f, q1 = 0.f;
        #pragma unroll
        for (int mt = 0; mt < 2; mt++) {
            #pragma unroll
            for (int hrow = 0; hrow < 2; hrow++) {
                int row = m0 + wm + mt * 16 + (lane >> 2) + hrow * 8;
                float v0 = acc[mt][nt][hrow * 2 + 0] + bv0;
                float v1 = acc[mt][nt][hrow * 2 + 1] + bv1;
                if (col < NDIM) {
                    float2 stv; stv.x = v0; stv.y = v1;
                    *(float2*)(g_agg + (size_t)row * EMB + col) = stv;
                }
                if (row < N_NODES) {
                    s0 += v0; q0 += v0 * v0;
                    s1 += v1; q1 += v1 * v1;
                }
            }
        }
        #pragma unroll
        for (int d = 4; d < 32; d <<= 1) {
            s0 += __shfl_xor_sync(0xffffffffu, s0, d);
            q0 += __shfl_xor_sync(0xffffffffu, q0, d);
            s1 += __shfl_xor_sync(0xffffffffu, s1, d);
            q1 += __shfl_xor_sync(0xffffffffu, q1, d);
        }
        if (lane < 4) {
            float* p = red + ((wid * 8 + nt) * 4 + lane) * 4;
            p[0] = s0; p[1] = q0; p[2] = s1; p[3] = q1;
        }
    }
    __syncthreads();
    // final cross-warp reduce: 32 threads, one per (nt, L) col-pair
    if (tid < 32) {
        int nt = tid >> 2, L = tid & 3;
        float s0 = 0.f, q0 = 0.f, s1 = 0.f, q1 = 0.f;
        #pragma unroll
        for (int w = 0; w < 8; w++) {
            const float* p = red + ((w * 8 + nt) * 4 + L) * 4;
            s0 += p[0]; q0 += p[1]; s1 += p[2]; q1 += p[3];
        }
        int col = n0 + nt * 8 + L * 2;
        int bx = blockIdx.x;
        if (col < NDIM) {
            g_part[bx * 2 * EMB + col]       = s0;
            g_part[bx * 2 * EMB + EMB + col] = q0;
        }
        if (col + 1 < NDIM) {
            g_part[bx * 2 * EMB + col + 1]       = s1;
            g_part[bx * 2 * EMB + EMB + col + 1] = q1;
        }
    }
}

// ---------------------------------------------------------------------------
__global__ void bn_final_kernel(const float* __restrict__ gamma,
                                const float* __restrict__ beta, int layer) {
    int c = threadIdx.x;
    if (c >= EMB) return;
    float s = 0.f, q = 0.f;
    for (int b = 0; b < NCHUNK; b++) {
        s += g_part[b * 2 * EMB + c];
        q += g_part[b * 2 * EMB + EMB + c];
    }
    const float inv_n = 1.0f / (float)N_NODES;
    float mean = s * inv_n;
    float var  = q * inv_n - mean * mean;
    float sc = gamma[layer * EMB + c] * rsqrtf(var + 1e-5f);
    float sh = beta[layer * EMB + c] - mean * sc;
    g_stats[c]       = sc;
    g_stats[EMB + c] = sh;
}
__global__ void bn_apply_kernel(float* __restrict__ dst) {   // final layer
    int idx = blockIdx.x * blockDim.x + threadIdx.x;
    if (idx >= N_NODES * 75) return;
    int c = (idx % 75) * 4;
    float4 v = ((const float4*)g_agg)[idx];
    float4 r;
    r.x = v.x * g_stats[c + 0] + g_stats[EMB + c + 0];
    r.y = v.y * g_stats[c + 1] + g_stats[EMB + c + 1];
    r.z = v.z * g_stats[c + 2] + g_stats[EMB + c + 2];
    r.w = v.w * g_stats[c + 3] + g_stats[EMB + c + 3];
    ((float4*)dst)[idx] = r;
}

// ---------------------------------------------------------------------------
extern "C" void kernel_launch(void* const* d_in, const int* in_sizes, int n_in,
                              void* d_out, int out_size) {
    const int*   x     = (const int*)d_in[0];
    const int*   ei    = (const int*)d_in[1];
    const int*   ea    = (const int*)d_in[2];
    const float* xemb  = (const float*)d_in[3];
    const float* eemb  = (const float*)d_in[4];
    const float* W1    = (const float*)d_in[5];
    const float* b1    = (const float*)d_in[6];
    const float* W2    = (const float*)d_in[7];
    const float* b2    = (const float*)d_in[8];
    const float* gamma = (const float*)d_in[9];
    const float* beta  = (const float*)d_in[10];
    float* out = (float*)d_out;

    cudaFuncSetAttribute(gemm1_kernel,
                         cudaFuncAttributeMaxDynamicSharedMemorySize, GEMM1_SMEM);
    cudaFuncSetAttribute(gemm2_kernel,
                         cudaFuncAttributeMaxDynamicSharedMemorySize, GEMM2_SMEM);

    node_emb_kernel<<<(N_NODES * 75 + 255) / 256, 256>>>(x, xemb);
    prep_w1_kernel<<<(NLAYER * NP1 * KP1 + 255) / 256, 256>>>(W1);
    prep_w2_kernel<<<(NLAYER * NP2 * KP2 + 255) / 256, 256>>>(W2);

    reset_kernel<<<(N_NODES + 255) / 256, 256>>>();
    hist_kernel<<<(N_EDGES + 255) / 256, 256>>>(ei, ea);
    scan1_kernel<<<NBLK256, 256>>>();
    scan2_kernel<<<1, 256>>>();
    scan3_kernel<<<NBLK256, 256>>>();
    fill_kernel<<<(N_EDGES + 255) / 256, 256>>>(ei);
    sort_kernel<<<(N_NODES + 255) / 256, 256>>>();

    float* hsrc_first;
    cudaGetSymbolAddress((void**)&hsrc_first, g_h);
    float* hsrc_rest;
    cudaGetSymbolAddress((void**)&hsrc_rest, g_agg);

    const int ggrid = (N_NODES + GNODES - 1) / GNODES;
    for (int layer = 0; layer < NLAYER; layer++) {
        if (layer == 0)
            gather_kernel<false><<<ggrid, 160>>>(hsrc_first, eemb, layer);
        else
            gather_kernel<true ><<<ggrid, 160>>>(hsrc_rest, eemb, layer);
        gemm1_kernel<<<dim3(M_PAD / 128, NP1 / 128), 256, GEMM1_SMEM>>>(b1, layer);
        gemm2_kernel<<<dim3(M_PAD / 256, NP2 / 64), 256, GEMM2_SMEM>>>(b2, layer);
        bn_final_kernel<<<1, 320>>>(gamma, beta, layer);
    }
    bn_apply_kernel<<<(N_NODES * 75 + 255) / 256, 256>>>(out);
}